// round 6
// baseline (speedup 1.0000x reference)
#include <cuda_runtime.h>
#include <cstdint>

#define T_  3
#define H_  96
#define W_  96
#define C_  128
#define CK  128
#define NHEAD 8
#define DH  16
#define HW_ (H_*W_)
#define NT  (T_*HW_)        // 27648
#define QX  4
#define KPAD 132            // fp32 row stride
#define SLICE (24*KPAD)     // floats per y-slice (3 frames x 8 kx)
#define NSLOT 6
#define YSEG 16             // y rows per block
#define XS (W_/QX)          // 24 x-strips
#define YB (H_/YSEG)        // 6 y-segments

// GEMM smem layout (floats): xs_t 2 bufs x 32 x 68, then Pa/Pb ulonglong2 2x32x32
#define XST_STRIDE 68
#define XST_BUF (32*XST_STRIDE)                  // 2176 floats
#define GEMM_SMEM_BYTES (2*XST_BUF*4 + 2*2*32*32*16)   // 17408 + 65536 = 82944

typedef unsigned long long u64;

__device__ float g_Q[NT*CK];
__device__ float g_K[NT*CK];
__device__ float g_V[NT*CK];
__device__ float g_O[NT*CK];

// ---------------- f32x2 helpers ----------------
__device__ __forceinline__ u64 ffma2(u64 a, u64 b, u64 c) {
    u64 d; asm("fma.rn.f32x2 %0,%1,%2,%3;" : "=l"(d) : "l"(a), "l"(b), "l"(c)); return d;
}
__device__ __forceinline__ u64 fadd2(u64 a, u64 b) {
    u64 d; asm("add.rn.f32x2 %0,%1,%2;" : "=l"(d) : "l"(a), "l"(b)); return d;
}
__device__ __forceinline__ u64 fmul2(u64 a, u64 b) {
    u64 d; asm("mul.rn.f32x2 %0,%1,%2;" : "=l"(d) : "l"(a), "l"(b)); return d;
}
__device__ __forceinline__ u64 pack2(float lo, float hi) {
    u64 d; asm("mov.b64 %0,{%1,%2};" : "=l"(d) : "f"(lo), "f"(hi)); return d;
}
__device__ __forceinline__ float2 unpack2(u64 v) {
    float2 r; asm("mov.b64 {%0,%1},%2;" : "=f"(r.x), "=f"(r.y) : "l"(v)); return r;
}
__device__ __forceinline__ void cp16(uint32_t dst, const float* src) {
    asm volatile("cp.async.cg.shared.global [%0], [%1], 16;" :: "r"(dst), "l"(src));
}

__device__ __forceinline__ float fexp(float x) {
    float t = fmaxf(x * 1.4426950408889634f, -125.0f);
    float r = t + 12582912.0f;
    float f = t - (r - 12582912.0f);
    int  ri = __float_as_int(r) - 0x4B400000;
    float p =              1.5403530393e-4f;
    p = fmaf(p, f, 1.3333558146e-3f);
    p = fmaf(p, f, 9.6181291076e-3f);
    p = fmaf(p, f, 5.5504108665e-2f);
    p = fmaf(p, f, 2.4022650696e-1f);
    p = fmaf(p, f, 6.9314718056e-1f);
    p = fmaf(p, f, 1.0f);
    return p * __int_as_float((ri + 127) << 23);
}

// ---------------------------------------------------------------------------
// Shared GEMM body: 64m x 128n, K=128, double-buffered, pre-dup'd B.
// Accumulators in acc[4][4] (m-pairs x n). Returns with results in acc.
// ---------------------------------------------------------------------------
struct GemmSmem {
    float* xs;          // 2 x 32 x 68
    ulonglong2* Pa;     // 2 x 32 x 32
    ulonglong2* Pb;     // 2 x 32 x 32
};

__device__ __forceinline__ void gemm_64x128(
    const float* __restrict__ A, const float* __restrict__ Wm,
    int m0, int tid, int tx, int ty, GemmSmem s, u64 acc[4][4])
{
    float4 xv[2], wv[4];

    // stage tile k0 into registers
    auto ldg_tile = [&](int k0) {
#pragma unroll
        for (int it = 0; it < 2; it++) {
            int idx = tid + it * 256, m = idx >> 3, k4 = idx & 7;
            xv[it] = *(const float4*)&A[(size_t)(m0 + m) * 128 + k0 + k4 * 4];
        }
#pragma unroll
        for (int it = 0; it < 4; it++) {
            int idx = tid + it * 256, k = idx >> 5, c4 = idx & 31;
            wv[it] = *(const float4*)&Wm[(size_t)k * 128 + c4 * 4 + (size_t)k0 * 128];
        }
    };
    auto sts_tile = [&](int b) {
#pragma unroll
        for (int it = 0; it < 2; it++) {
            int idx = tid + it * 256, m = idx >> 3, k4 = idx & 7;
            float* xb = s.xs + b * XST_BUF;
            xb[(k4 * 4 + 0) * XST_STRIDE + m] = xv[it].x;
            xb[(k4 * 4 + 1) * XST_STRIDE + m] = xv[it].y;
            xb[(k4 * 4 + 2) * XST_STRIDE + m] = xv[it].z;
            xb[(k4 * 4 + 3) * XST_STRIDE + m] = xv[it].w;
        }
#pragma unroll
        for (int it = 0; it < 4; it++) {
            int idx = tid + it * 256, k = idx >> 5, c4 = idx & 31;
            ulonglong2 pa, pb;
            pa.x = pack2(wv[it].x, wv[it].x);
            pa.y = pack2(wv[it].y, wv[it].y);
            pb.x = pack2(wv[it].z, wv[it].z);
            pb.y = pack2(wv[it].w, wv[it].w);
            s.Pa[b * 1024 + k * 32 + c4] = pa;
            s.Pb[b * 1024 + k * 32 + c4] = pb;
        }
    };

    ldg_tile(0);
    sts_tile(0);
    __syncthreads();

#pragma unroll
    for (int kt = 0; kt < 4; kt++) {
        if (kt < 3) ldg_tile((kt + 1) * 32);
        const int b = kt & 1;
        const float* xb = s.xs + b * XST_BUF;
        const ulonglong2* Pab = s.Pa + b * 1024;
        const ulonglong2* Pbb = s.Pb + b * 1024;
#pragma unroll
        for (int kk = 0; kk < 32; kk++) {
            ulonglong2 bp01 = Pab[kk * 32 + tx];
            ulonglong2 bp23 = Pbb[kk * 32 + tx];
            ulonglong2 a01 = *(const ulonglong2*)&xb[kk * XST_STRIDE + ty * 8];
            ulonglong2 a23 = *(const ulonglong2*)&xb[kk * XST_STRIDE + ty * 8 + 4];
            acc[0][0] = ffma2(a01.x, bp01.x, acc[0][0]);
            acc[0][1] = ffma2(a01.x, bp01.y, acc[0][1]);
            acc[0][2] = ffma2(a01.x, bp23.x, acc[0][2]);
            acc[0][3] = ffma2(a01.x, bp23.y, acc[0][3]);
            acc[1][0] = ffma2(a01.y, bp01.x, acc[1][0]);
            acc[1][1] = ffma2(a01.y, bp01.y, acc[1][1]);
            acc[1][2] = ffma2(a01.y, bp23.x, acc[1][2]);
            acc[1][3] = ffma2(a01.y, bp23.y, acc[1][3]);
            acc[2][0] = ffma2(a23.x, bp01.x, acc[2][0]);
            acc[2][1] = ffma2(a23.x, bp01.y, acc[2][1]);
            acc[2][2] = ffma2(a23.x, bp23.x, acc[2][2]);
            acc[2][3] = ffma2(a23.x, bp23.y, acc[2][3]);
            acc[3][0] = ffma2(a23.y, bp01.x, acc[3][0]);
            acc[3][1] = ffma2(a23.y, bp01.y, acc[3][1]);
            acc[3][2] = ffma2(a23.y, bp23.x, acc[3][2]);
            acc[3][3] = ffma2(a23.y, bp23.y, acc[3][3]);
        }
        if (kt < 3) {
            sts_tile((kt + 1) & 1);
            __syncthreads();
        }
    }
}

// ---------------------------------------------------------------------------
// Kernel 1: QKV projection + embedding epilogue.
// ---------------------------------------------------------------------------
__global__ __launch_bounds__(256) void qkv_kernel(
    const float* __restrict__ x,
    const float* __restrict__ Wq,
    const float* __restrict__ Wk,
    const float* __restrict__ Wv,
    const float* __restrict__ temp_emb,
    const float* __restrict__ sp_emb)
{
    extern __shared__ float smraw[];
    GemmSmem s;
    s.xs = smraw;
    s.Pa = (ulonglong2*)(smraw + 2 * XST_BUF);
    s.Pb = s.Pa + 2048;

    const int which = blockIdx.y;
    const float* Wm = (which == 0) ? Wq : (which == 1) ? Wk : Wv;
    float* dst      = (which == 0) ? g_Q : (which == 1) ? g_K : g_V;

    const int m0  = blockIdx.x * 64;
    const int tid = threadIdx.x;
    const int tx  = tid & 31;
    const int ty  = tid >> 5;

    u64 acc[4][4];
#pragma unroll
    for (int p = 0; p < 4; p++)
#pragma unroll
        for (int j = 0; j < 4; j++) acc[p][j] = 0ull;

    gemm_64x128(x, Wm, m0, tid, tx, ty, s, acc);

    const int col0 = tx * 4;
#pragma unroll
    for (int p = 0; p < 4; p++) {
        float2 c0 = unpack2(acc[p][0]);
        float2 c1 = unpack2(acc[p][1]);
        float2 c2 = unpack2(acc[p][2]);
        float2 c3 = unpack2(acc[p][3]);
        float rowv[2][4] = {{c0.x, c1.x, c2.x, c3.x}, {c0.y, c1.y, c2.y, c3.y}};
#pragma unroll
        for (int rr = 0; rr < 2; rr++) {
            const int n   = m0 + ty * 8 + 2 * p + rr;
            const int t   = n / HW_;
            const int rem = n % HW_;
            if (which <= 1) {
#pragma unroll
                for (int j = 0; j < 4; j++) rowv[rr][j] += temp_emb[t * CK + col0 + j];
            }
            if (which == 0) {
                const int yq = rem / W_;
                const int xq = rem % W_;
                const int yc = min(max(yq, 2), H_ - 3);
                const int xc = min(max(xq, 2), W_ - 3);
                const int qidx = (yq - yc + 2) * 5 + (xq - xc + 2);
#pragma unroll
                for (int j = 0; j < 4; j++) rowv[rr][j] += sp_emb[qidx * CK + col0 + j];
            }
            *(float4*)&dst[(size_t)n * CK + col0] =
                make_float4(rowv[rr][0], rowv[rr][1], rowv[rr][2], rowv[rr][3]);
        }
    }
}

// ---------------------------------------------------------------------------
// Kernel 2: attention, rolling-window persistent blocks (R4 version).
// ---------------------------------------------------------------------------
__global__ __launch_bounds__(768) void attn_kernel(const float* __restrict__ sp_emb)
{
    extern __shared__ float sm[];
    float* Kr  = sm;                        // NSLOT x 24 x KPAD
    float* Vr  = Kr + NSLOT * SLICE;
    float* SPs = Vr + NSLOT * SLICE;        // 25 x KPAD

    const uint32_t sbase = (uint32_t)__cvta_generic_to_shared(sm);
    const uint32_t Kb  = sbase;
    const uint32_t Vb  = sbase + NSLOT * SLICE * 4;
    const uint32_t SPb = Vb + NSLOT * SLICE * 4;

    const int x0  = blockIdx.x * QX;
    const int y0  = blockIdx.y * YSEG;
    const int tid = threadIdx.x;
    const int xbase = min(max(x0, 2), W_ - 3) - 2;

    const int srow = tid >> 5;              // 0..23  = t*8 + kx
    const int sc4  = (tid & 31) * 4;
    const int st   = srow >> 3;
    const int scol = min(xbase + (srow & 7), W_ - 1);
    const size_t sgbase = (size_t)(st * HW_ + scol) * CK + sc4;
    const uint32_t ssoff = (srow * KPAD + sc4) * 4;

    for (int i = tid; i < 25 * 32; i += 768) {
        int p = i >> 5, c4 = (i & 31) * 4;
        cp16(SPb + (uint32_t)(p * KPAD + c4) * 4, &sp_emb[p * 128 + c4]);
    }
    const int yc0 = min(max(y0, 2), H_ - 3);
#pragma unroll
    for (int r = 0; r < 5; r++) {
        const int yr = yc0 - 2 + r;
        const uint32_t so = (uint32_t)((yr % NSLOT) * SLICE * 4) + ssoff;
        const size_t g = sgbase + (size_t)yr * W_ * CK;
        cp16(Kb + so, &g_K[g]);
        cp16(Vb + so, &g_V[g]);
    }
    asm volatile("cp.async.commit_group;");
    asm volatile("cp.async.wait_group 0;");
    __syncthreads();
    int loaded_max = yc0 + 2;

    const int lane = tid & 31;
    const int w    = tid >> 5;
    const int tq   = w / NHEAD;
    const int h    = w % NHEAD;
    const int hoff = h * DH;

    const int qx  = lane >> 3;
    const int rl  = lane & 7;
    const int xoffq = min(max(x0 + qx, 2), W_ - 3) - 2 - xbase;   // 0..3
    const int kxr   = rl - xoffq;
    const bool valid = (kxr >= 0) && (kxr <= 4);
    const int kxrc  = min(max(kxr, 0), 4);
    const int d4 = lane >> 3;

    for (int yq = y0; yq < y0 + YSEG; yq++) {
        const int yc = min(max(yq, 2), H_ - 3);

        const int need_next = min(max(yq + 1, 2), H_ - 3) + 2;
        const bool pf = (yq + 1 < y0 + YSEG) && (need_next > loaded_max);
        if (pf) {
            const uint32_t so = (uint32_t)((need_next % NSLOT) * SLICE * 4) + ssoff;
            const size_t g = sgbase + (size_t)need_next * W_ * CK;
            cp16(Kb + so, &g_K[g]);
            cp16(Vb + so, &g_V[g]);
            asm volatile("cp.async.commit_group;");
            loaded_max = need_next;
        }

        int slot[5];
        {
            int s0 = (yc - 2) % NSLOT;
#pragma unroll
            for (int i5 = 0; i5 < 5; i5++) {
                slot[i5] = s0;
                s0 = (s0 + 1 == NSLOT) ? 0 : s0 + 1;
            }
        }

        const float* qp = &g_Q[(size_t)(tq * HW_ + yq * W_ + x0 + qx) * CK + hoff];
        ulonglong2 qA = *(const ulonglong2*)&qp[0];
        ulonglong2 qB = *(const ulonglong2*)&qp[4];
        ulonglong2 qC = *(const ulonglong2*)&qp[8];
        ulonglong2 qD = *(const ulonglong2*)&qp[12];

        float a[15];
#pragma unroll
        for (int tk = 0; tk < 3; tk++) {
#pragma unroll
            for (int i5 = 0; i5 < 5; i5++) {
                const float* kr = &Kr[slot[i5] * SLICE + (tk * 8 + rl) * KPAD + hoff];
                ulonglong2 k0 = *(const ulonglong2*)&kr[0];
                ulonglong2 k1 = *(const ulonglong2*)&kr[4];
                ulonglong2 k2 = *(const ulonglong2*)&kr[8];
                ulonglong2 k3 = *(const ulonglong2*)&kr[12];
                u64 s = ffma2(qA.x, k0.x, 0ull);
                s = ffma2(qA.y, k0.y, s);
                s = ffma2(qB.x, k1.x, s);
                s = ffma2(qB.y, k1.y, s);
                s = ffma2(qC.x, k2.x, s);
                s = ffma2(qC.y, k2.y, s);
                s = ffma2(qD.x, k3.x, s);
                s = ffma2(qD.y, k3.y, s);
                float2 f = unpack2(s);
                a[tk * 5 + i5] = f.x + f.y;
            }
        }

        float qsp[5];
#pragma unroll
        for (int i5 = 0; i5 < 5; i5++) {
            const float* sp = &SPs[(i5 * 5 + kxrc) * KPAD + hoff];
            ulonglong2 s0 = *(const ulonglong2*)&sp[0];
            ulonglong2 s1 = *(const ulonglong2*)&sp[4];
            ulonglong2 s2 = *(const ulonglong2*)&sp[8];
            ulonglong2 s3 = *(const ulonglong2*)&sp[12];
            u64 s = ffma2(qA.x, s0.x, 0ull);
            s = ffma2(qA.y, s0.y, s);
            s = ffma2(qB.x, s1.x, s);
            s = ffma2(qB.y, s1.y, s);
            s = ffma2(qC.x, s2.x, s);
            s = ffma2(qC.y, s2.y, s);
            s = ffma2(qD.x, s3.x, s);
            s = ffma2(qD.y, s3.y, s);
            float2 f = unpack2(s);
            qsp[i5] = f.x + f.y;
        }

        float ssum = 0.f;
#pragma unroll
        for (int tk = 0; tk < 3; tk++)
#pragma unroll
            for (int i5 = 0; i5 < 5; i5++) {
                int idx = tk * 5 + i5;
                float s = (a[idx] + qsp[i5]) * 0.25f;
                float e = valid ? fexp(s) : 0.f;
                a[idx] = e;
                ssum += e;
            }
        ssum += __shfl_xor_sync(0xffffffffu, ssum, 1);
        ssum += __shfl_xor_sync(0xffffffffu, ssum, 2);
        ssum += __shfl_xor_sync(0xffffffffu, ssum, 4);
        float rs = __fdividef(1.f, ssum);

        // phase 2: AV
        u64 acc[4][2];
#pragma unroll
        for (int q = 0; q < 4; q++) { acc[q][0] = 0ull; acc[q][1] = 0ull; }

#pragma unroll
        for (int tk = 0; tk < 3; tk++) {
#pragma unroll
            for (int i5 = 0; i5 < 5; i5++) {
                const int idx = tk * 5 + i5;
                const float* vrp = &Vr[slot[i5] * SLICE + (tk * 8 + rl) * KPAD + hoff + d4 * 4];
                ulonglong2 v = *(const ulonglong2*)vrp;
#pragma unroll
                for (int q = 0; q < 4; q++) {
                    float av = __shfl_sync(0xffffffffu, a[idx], (q << 3) | rl);
                    u64 aa = pack2(av, av);
                    acc[q][0] = ffma2(aa, v.x, acc[q][0]);
                    acc[q][1] = ffma2(aa, v.y, acc[q][1]);
                }
            }
        }
#pragma unroll
        for (int off = 1; off <= 4; off <<= 1) {
#pragma unroll
            for (int q = 0; q < 4; q++) {
                acc[q][0] = fadd2(acc[q][0], __shfl_xor_sync(0xffffffffu, acc[q][0], off));
                acc[q][1] = fadd2(acc[q][1], __shfl_xor_sync(0xffffffffu, acc[q][1], off));
            }
        }
        float rsw = __shfl_sync(0xffffffffu, rs, (lane & 7) * 8);
        if (rl < 4) {
            float2 lo = unpack2(acc[rl][0]);
            float2 hi = unpack2(acc[rl][1]);
            float4 o = make_float4(lo.x * rsw, lo.y * rsw, hi.x * rsw, hi.y * rsw);
            *(float4*)&g_O[(size_t)(tq * HW_ + yq * W_ + x0 + rl) * CK + hoff + d4 * 4] = o;
        }

        if (pf) asm volatile("cp.async.wait_group 0;");
        __syncthreads();
    }
}

// ---------------------------------------------------------------------------
// Kernel 3: output projection O @ Wo, transposed writeout.
// ---------------------------------------------------------------------------
__global__ __launch_bounds__(256) void outproj_kernel(
    const float* __restrict__ Wo, float* __restrict__ out)
{
    extern __shared__ float smraw[];
    GemmSmem s;
    s.xs = smraw;
    s.Pa = (ulonglong2*)(smraw + 2 * XST_BUF);
    s.Pb = s.Pa + 2048;

    const int m0  = blockIdx.x * 64;
    const int tid = threadIdx.x;
    const int tx  = tid & 31;
    const int ty  = tid >> 5;

    u64 acc[4][4];
#pragma unroll
    for (int p = 0; p < 4; p++)
#pragma unroll
        for (int j = 0; j < 4; j++) acc[p][j] = 0ull;

    gemm_64x128(g_O, Wo, m0, tid, tx, ty, s, acc);

    const int col0 = tx * 4;
#pragma unroll
    for (int p = 0; p < 4; p++) {
        float2 c0 = unpack2(acc[p][0]);
        float2 c1 = unpack2(acc[p][1]);
        float2 c2 = unpack2(acc[p][2]);
        float2 c3 = unpack2(acc[p][3]);
        float rowv[2][4] = {{c0.x, c1.x, c2.x, c3.x}, {c0.y, c1.y, c2.y, c3.y}};
#pragma unroll
        for (int rr = 0; rr < 2; rr++) {
            const int n   = m0 + ty * 8 + 2 * p + rr;
            const int t   = n / HW_;
            const int rem = n % HW_;
            const size_t o = (size_t)rem * (T_ * C_) + t * C_ + col0;
            *(float4*)&out[o] =
                make_float4(rowv[rr][0], rowv[rr][1], rowv[rr][2], rowv[rr][3]);
        }
    }
}

// ---------------------------------------------------------------------------
extern "C" void kernel_launch(void* const* d_in, const int* in_sizes, int n_in,
                              void* d_out, int out_size)
{
    const float* x    = (const float*)d_in[0];
    const float* Wq   = (const float*)d_in[1];
    const float* Wk   = (const float*)d_in[2];
    const float* Wv   = (const float*)d_in[3];
    const float* Wo   = (const float*)d_in[4];
    const float* temp = (const float*)d_in[5];
    const float* sp   = (const float*)d_in[6];
    float* out = (float*)d_out;

    cudaFuncSetAttribute(qkv_kernel, cudaFuncAttributeMaxDynamicSharedMemorySize, GEMM_SMEM_BYTES);
    cudaFuncSetAttribute(outproj_kernel, cudaFuncAttributeMaxDynamicSharedMemorySize, GEMM_SMEM_BYTES);

    qkv_kernel<<<dim3(NT / 64, 3), 256, GEMM_SMEM_BYTES>>>(x, Wq, Wk, Wv, temp, sp);

    const size_t smem = (size_t)(2 * NSLOT * SLICE + 25 * KPAD) * sizeof(float);
    cudaFuncSetAttribute(attn_kernel, cudaFuncAttributeMaxDynamicSharedMemorySize, (int)smem);
    attn_kernel<<<dim3(XS, YB), 768, smem>>>(sp);

    outproj_kernel<<<NT / 64, 256, GEMM_SMEM_BYTES>>>(Wo, out);
}

// round 9
// speedup vs baseline: 1.1440x; 1.1440x over previous
#include <cuda_runtime.h>
#include <cuda_bf16.h>
#include <cstdint>

#define T_  3
#define H_  96
#define W_  96
#define C_  128
#define CK  128
#define NHEAD 8
#define DH  16
#define HW_ (H_*W_)
#define NT  (T_*HW_)        // 27648
#define QX  4
#define KPAD 132
#define SLICE (24*KPAD)
#define NSLOT 6
#define YSEG 16
#define XS (W_/QX)
#define YB (H_/YSEG)

typedef unsigned long long u64;

extern __shared__ char smraw[];

__device__ float g_Q[NT*CK];
__device__ float g_K[NT*CK];
__device__ float g_V[NT*CK];

// packed bf16 pairs (2 per uint32), row-major with 64 pairs per row of 128
__device__ uint32_t g_xhi[NT*64], g_xlo[NT*64];
__device__ uint32_t g_Ohi[NT*64], g_Olo[NT*64];
__device__ uint32_t g_Whi[4][128*64], g_Wlo[4][128*64];   // [k][n-pairs]

// ---------------- helpers ----------------
__device__ __forceinline__ u64 ffma2(u64 a, u64 b, u64 c) {
    u64 d; asm("fma.rn.f32x2 %0,%1,%2,%3;" : "=l"(d) : "l"(a), "l"(b), "l"(c)); return d;
}
__device__ __forceinline__ u64 fadd2(u64 a, u64 b) {
    u64 d; asm("add.rn.f32x2 %0,%1,%2;" : "=l"(d) : "l"(a), "l"(b)); return d;
}
__device__ __forceinline__ u64 pack2(float lo, float hi) {
    u64 d; asm("mov.b64 %0,{%1,%2};" : "=l"(d) : "f"(lo), "f"(hi)); return d;
}
__device__ __forceinline__ float2 unpack2(u64 v) {
    float2 r; asm("mov.b64 {%0,%1},%2;" : "=f"(r.x), "=f"(r.y) : "l"(v)); return r;
}
__device__ __forceinline__ void cp16(uint32_t dst, const void* src) {
    asm volatile("cp.async.cg.shared.global [%0], [%1], 16;" :: "r"(dst), "l"(src));
}
__device__ __forceinline__ void split2(float x0, float x1, uint32_t& h, uint32_t& l) {
    __nv_bfloat16 h0 = __float2bfloat16(x0);
    __nv_bfloat16 h1 = __float2bfloat16(x1);
    __nv_bfloat16 l0 = __float2bfloat16(x0 - __bfloat162float(h0));
    __nv_bfloat16 l1 = __float2bfloat16(x1 - __bfloat162float(h1));
    h = ((uint32_t)__bfloat16_as_ushort(h1) << 16) | __bfloat16_as_ushort(h0);
    l = ((uint32_t)__bfloat16_as_ushort(l1) << 16) | __bfloat16_as_ushort(l0);
}

__device__ __forceinline__ float fexp(float x) {
    float t = fmaxf(x * 1.4426950408889634f, -125.0f);
    float r = t + 12582912.0f;
    float f = t - (r - 12582912.0f);
    int  ri = __float_as_int(r) - 0x4B400000;
    float p =              1.5403530393e-4f;
    p = fmaf(p, f, 1.3333558146e-3f);
    p = fmaf(p, f, 9.6181291076e-3f);
    p = fmaf(p, f, 5.5504108665e-2f);
    p = fmaf(p, f, 2.4022650696e-1f);
    p = fmaf(p, f, 6.9314718056e-1f);
    p = fmaf(p, f, 1.0f);
    return p * __int_as_float((ri + 127) << 23);
}

// ---------------- mma helpers ----------------
__device__ __forceinline__ void ldsm_x4(uint32_t* a, uint32_t addr) {
    asm volatile("ldmatrix.sync.aligned.m8n8.x4.shared.b16 {%0,%1,%2,%3}, [%4];"
                 : "=r"(a[0]), "=r"(a[1]), "=r"(a[2]), "=r"(a[3]) : "r"(addr));
}
__device__ __forceinline__ void ldsm_x2t(uint32_t* b, uint32_t addr) {
    asm volatile("ldmatrix.sync.aligned.m8n8.x2.trans.shared.b16 {%0,%1}, [%2];"
                 : "=r"(b[0]), "=r"(b[1]) : "r"(addr));
}
__device__ __forceinline__ void mma16816(float* c, const uint32_t* a, const uint32_t* b) {
    asm volatile(
        "mma.sync.aligned.m16n8k16.row.col.f32.bf16.bf16.f32 "
        "{%0,%1,%2,%3}, {%4,%5,%6,%7}, {%8,%9}, {%0,%1,%2,%3};"
        : "+f"(c[0]), "+f"(c[1]), "+f"(c[2]), "+f"(c[3])
        : "r"(a[0]), "r"(a[1]), "r"(a[2]), "r"(a[3]), "r"(b[0]), "r"(b[1]));
}

// smem: 4 tiles of 128 rows x 272 bytes (136 bf16 stride)
#define BROW 272
#define TILE_B (128*BROW)       // 34816
#define AHI_OFF 0
#define ALO_OFF TILE_B
#define BHI_OFF (2*TILE_B)
#define BLO_OFF (3*TILE_B)
#define GEMM_SMEM (4*TILE_B)    // 139264

// ---------------------------------------------------------------------------
// prep kernels
// ---------------------------------------------------------------------------
__global__ __launch_bounds__(256) void xprep_kernel(const float* __restrict__ x) {
    int i = blockIdx.x * 256 + threadIdx.x;      // one float4 = 2 pairs
    float4 v = *(const float4*)&x[(size_t)i * 4];
    uint32_t h0, l0, h1, l1;
    split2(v.x, v.y, h0, l0);
    split2(v.z, v.w, h1, l1);
    *(uint2*)&g_xhi[i * 2] = make_uint2(h0, h1);
    *(uint2*)&g_xlo[i * 2] = make_uint2(l0, l1);
}

__global__ __launch_bounds__(256) void wprep_kernel(
    const float* __restrict__ Wq, const float* __restrict__ Wk,
    const float* __restrict__ Wv, const float* __restrict__ Wo)
{
    const int mat = blockIdx.x;
    const float* Wsrc = (mat == 0) ? Wq : (mat == 1) ? Wk : (mat == 2) ? Wv : Wo;
    for (int p = threadIdx.x; p < 128 * 64; p += 256) {
        float2 v = *(const float2*)&Wsrc[(size_t)p * 2];   // row-major [k][n]
        uint32_t h, l;
        split2(v.x, v.y, h, l);
        g_Whi[mat][p] = h;
        g_Wlo[mat][p] = l;
    }
}

// ---------------------------------------------------------------------------
// Shared MMA body: fills smem via cp.async, computes c[2][8][4] per warp.
// Warp layout: wm = w&3 (32-row group), wn = w>>2 (64-col group).
// ---------------------------------------------------------------------------
__device__ __forceinline__ void mma_body(
    const uint32_t* __restrict__ Ahi, const uint32_t* __restrict__ Alo,
    int mat, int m0, float c[2][8][4])
{
    const int tid  = threadIdx.x;
    const int w    = tid >> 5;
    const int lane = tid & 31;
    const uint32_t sb = (uint32_t)__cvta_generic_to_shared(smraw);

    // fill: 128 rows x 16 chunks(16B) per tile
#pragma unroll
    for (int it = 0; it < 8; it++) {
        int i = tid + it * 256;
        int r = i >> 4, ch = i & 15;
        uint32_t d = (uint32_t)(r * BROW + ch * 16);
        cp16(sb + AHI_OFF + d, (const char*)Ahi + ((size_t)(m0 + r) * 64 + ch * 4) * 4);
        cp16(sb + ALO_OFF + d, (const char*)Alo + ((size_t)(m0 + r) * 64 + ch * 4) * 4);
        cp16(sb + BHI_OFF + d, (const char*)&g_Whi[mat][r * 64 + ch * 4]);
        cp16(sb + BLO_OFF + d, (const char*)&g_Wlo[mat][r * 64 + ch * 4]);
    }
    asm volatile("cp.async.commit_group;");
    asm volatile("cp.async.wait_group 0;");
    __syncthreads();

#pragma unroll
    for (int mt = 0; mt < 2; mt++)
#pragma unroll
        for (int nt = 0; nt < 8; nt++)
#pragma unroll
            for (int j = 0; j < 4; j++) c[mt][nt][j] = 0.f;

    const int wm = w & 3, wn = w >> 2;
    // per-lane base addresses (bytes)
    const uint32_t aBase = sb + (uint32_t)((wm * 32 + (lane & 15)) * BROW + (lane >> 4) * 16);
    const uint32_t bBase = sb + (uint32_t)((lane & 15) * BROW + wn * 128);

    const uint32_t aOffP[3] = {AHI_OFF, AHI_OFF, ALO_OFF};
    const uint32_t bOffP[3] = {BHI_OFF, BLO_OFF, BHI_OFF};

#pragma unroll
    for (int pass = 0; pass < 3; pass++) {
        const uint32_t aT = aBase + aOffP[pass];
        const uint32_t bT = bBase + bOffP[pass];
#pragma unroll
        for (int k8 = 0; k8 < 8; k8++) {
            uint32_t a[2][4], b[8][2];
#pragma unroll
            for (int mt = 0; mt < 2; mt++)
                ldsm_x4(a[mt], aT + (uint32_t)(mt * 16 * BROW + k8 * 32));
#pragma unroll
            for (int nt = 0; nt < 8; nt++)
                ldsm_x2t(b[nt], bT + (uint32_t)(k8 * 16 * BROW + nt * 16));
#pragma unroll
            for (int mt = 0; mt < 2; mt++)
#pragma unroll
                for (int nt = 0; nt < 8; nt++)
                    mma16816(c[mt][nt], a[mt], b[nt]);
        }
    }
}

// ---------------------------------------------------------------------------
// Kernel: QKV via mma.sync + embedding epilogue. grid (216, 3)
// ---------------------------------------------------------------------------
__global__ __launch_bounds__(256, 1) void qkv_mma_kernel(
    const float* __restrict__ temp_emb, const float* __restrict__ sp_emb)
{
    const int mat = blockIdx.y;
    float* dst = (mat == 0) ? g_Q : (mat == 1) ? g_K : g_V;
    const int m0 = blockIdx.x * 128;

    float c[2][8][4];
    mma_body(g_xhi, g_xlo, mat, m0, c);

    const int w = threadIdx.x >> 5, lane = threadIdx.x & 31;
    const int wm = w & 3, wn = w >> 2;
#pragma unroll
    for (int mt = 0; mt < 2; mt++) {
#pragma unroll
        for (int rh = 0; rh < 2; rh++) {
            const int n   = m0 + wm * 32 + mt * 16 + (lane >> 2) + rh * 8;
            const int t   = n / HW_;
            const int rem = n % HW_;
            int qidx = 0;
            if (mat == 0) {
                const int yq = rem / W_, xq = rem % W_;
                const int yc = min(max(yq, 2), H_ - 3);
                const int xc = min(max(xq, 2), W_ - 3);
                qidx = (yq - yc + 2) * 5 + (xq - xc + 2);
            }
#pragma unroll
            for (int nt = 0; nt < 8; nt++) {
                const int col = wn * 64 + nt * 8 + 2 * (lane & 3);
                float v0 = c[mt][nt][rh * 2 + 0];
                float v1 = c[mt][nt][rh * 2 + 1];
                if (mat <= 1) {
                    v0 += temp_emb[t * CK + col];
                    v1 += temp_emb[t * CK + col + 1];
                }
                if (mat == 0) {
                    v0 += sp_emb[qidx * CK + col];
                    v1 += sp_emb[qidx * CK + col + 1];
                }
                *(float2*)&dst[(size_t)n * CK + col] = make_float2(v0, v1);
            }
        }
    }
}

// ---------------------------------------------------------------------------
// Kernel: output projection via mma.sync + transposed writeout. grid 216
// ---------------------------------------------------------------------------
__global__ __launch_bounds__(256, 1) void outproj_mma_kernel(float* __restrict__ out)
{
    const int m0 = blockIdx.x * 128;

    float c[2][8][4];
    mma_body(g_Ohi, g_Olo, 3, m0, c);

    const int w = threadIdx.x >> 5, lane = threadIdx.x & 31;
    const int wm = w & 3, wn = w >> 2;
#pragma unroll
    for (int mt = 0; mt < 2; mt++) {
#pragma unroll
        for (int rh = 0; rh < 2; rh++) {
            const int n   = m0 + wm * 32 + mt * 16 + (lane >> 2) + rh * 8;
            const int t   = n / HW_;
            const int rem = n % HW_;
            const size_t ob = (size_t)rem * (T_ * C_) + t * C_;
#pragma unroll
            for (int nt = 0; nt < 8; nt++) {
                const int col = wn * 64 + nt * 8 + 2 * (lane & 3);
                *(float2*)&out[ob + col] =
                    make_float2(c[mt][nt][rh * 2 + 0], c[mt][nt][rh * 2 + 1]);
            }
        }
    }
}

// ---------------------------------------------------------------------------
// Kernel: attention, rolling-window persistent blocks (R4), epilogue emits
// O as hi/lo bf16 packed pairs for the outproj MMA.
// ---------------------------------------------------------------------------
__global__ __launch_bounds__(768) void attn_kernel(const float* __restrict__ sp_emb)
{
    float* sm  = (float*)smraw;
    float* Kr  = sm;
    float* Vr  = Kr + NSLOT * SLICE;
    float* SPs = Vr + NSLOT * SLICE;

    const uint32_t sbase = (uint32_t)__cvta_generic_to_shared(sm);
    const uint32_t Kb  = sbase;
    const uint32_t Vb  = sbase + NSLOT * SLICE * 4;
    const uint32_t SPb = Vb + NSLOT * SLICE * 4;

    const int x0  = blockIdx.x * QX;
    const int y0  = blockIdx.y * YSEG;
    const int tid = threadIdx.x;
    const int xbase = min(max(x0, 2), W_ - 3) - 2;

    const int srow = tid >> 5;
    const int sc4  = (tid & 31) * 4;
    const int st   = srow >> 3;
    const int scol = min(xbase + (srow & 7), W_ - 1);
    const size_t sgbase = (size_t)(st * HW_ + scol) * CK + sc4;
    const uint32_t ssoff = (srow * KPAD + sc4) * 4;

    for (int i = tid; i < 25 * 32; i += 768) {
        int p = i >> 5, c4 = (i & 31) * 4;
        cp16(SPb + (uint32_t)(p * KPAD + c4) * 4, &sp_emb[p * 128 + c4]);
    }
    const int yc0 = min(max(y0, 2), H_ - 3);
#pragma unroll
    for (int r = 0; r < 5; r++) {
        const int yr = yc0 - 2 + r;
        const uint32_t so = (uint32_t)((yr % NSLOT) * SLICE * 4) + ssoff;
        const size_t g = sgbase + (size_t)yr * W_ * CK;
        cp16(Kb + so, &g_K[g]);
        cp16(Vb + so, &g_V[g]);
    }
    asm volatile("cp.async.commit_group;");
    asm volatile("cp.async.wait_group 0;");
    __syncthreads();
    int loaded_max = yc0 + 2;

    const int lane = tid & 31;
    const int w    = tid >> 5;
    const int tq   = w / NHEAD;
    const int h    = w % NHEAD;
    const int hoff = h * DH;

    const int qx  = lane >> 3;
    const int rl  = lane & 7;
    const int xoffq = min(max(x0 + qx, 2), W_ - 3) - 2 - xbase;
    const int kxr   = rl - xoffq;
    const bool valid = (kxr >= 0) && (kxr <= 4);
    const int kxrc  = min(max(kxr, 0), 4);
    const int d4 = lane >> 3;

    for (int yq = y0; yq < y0 + YSEG; yq++) {
        const int yc = min(max(yq, 2), H_ - 3);

        const int need_next = min(max(yq + 1, 2), H_ - 3) + 2;
        const bool pf = (yq + 1 < y0 + YSEG) && (need_next > loaded_max);
        if (pf) {
            const uint32_t so = (uint32_t)((need_next % NSLOT) * SLICE * 4) + ssoff;
            const size_t g = sgbase + (size_t)need_next * W_ * CK;
            cp16(Kb + so, &g_K[g]);
            cp16(Vb + so, &g_V[g]);
            asm volatile("cp.async.commit_group;");
            loaded_max = need_next;
        }

        int slot[5];
        {
            int s0 = (yc - 2) % NSLOT;
#pragma unroll
            for (int i5 = 0; i5 < 5; i5++) {
                slot[i5] = s0;
                s0 = (s0 + 1 == NSLOT) ? 0 : s0 + 1;
            }
        }

        const float* qp = &g_Q[(size_t)(tq * HW_ + yq * W_ + x0 + qx) * CK + hoff];
        ulonglong2 qA = *(const ulonglong2*)&qp[0];
        ulonglong2 qB = *(const ulonglong2*)&qp[4];
        ulonglong2 qC = *(const ulonglong2*)&qp[8];
        ulonglong2 qD = *(const ulonglong2*)&qp[12];

        float a[15];
#pragma unroll
        for (int tk = 0; tk < 3; tk++) {
#pragma unroll
            for (int i5 = 0; i5 < 5; i5++) {
                const float* kr = &Kr[slot[i5] * SLICE + (tk * 8 + rl) * KPAD + hoff];
                ulonglong2 k0 = *(const ulonglong2*)&kr[0];
                ulonglong2 k1 = *(const ulonglong2*)&kr[4];
                ulonglong2 k2 = *(const ulonglong2*)&kr[8];
                ulonglong2 k3 = *(const ulonglong2*)&kr[12];
                u64 s = ffma2(qA.x, k0.x, 0ull);
                s = ffma2(qA.y, k0.y, s);
                s = ffma2(qB.x, k1.x, s);
                s = ffma2(qB.y, k1.y, s);
                s = ffma2(qC.x, k2.x, s);
                s = ffma2(qC.y, k2.y, s);
                s = ffma2(qD.x, k3.x, s);
                s = ffma2(qD.y, k3.y, s);
                float2 f = unpack2(s);
                a[tk * 5 + i5] = f.x + f.y;
            }
        }

        float qsp[5];
#pragma unroll
        for (int i5 = 0; i5 < 5; i5++) {
            const float* sp = &SPs[(i5 * 5 + kxrc) * KPAD + hoff];
            ulonglong2 s0 = *(const ulonglong2*)&sp[0];
            ulonglong2 s1 = *(const ulonglong2*)&sp[4];
            ulonglong2 s2 = *(const ulonglong2*)&sp[8];
            ulonglong2 s3 = *(const ulonglong2*)&sp[12];
            u64 s = ffma2(qA.x, s0.x, 0ull);
            s = ffma2(qA.y, s0.y, s);
            s = ffma2(qB.x, s1.x, s);
            s = ffma2(qB.y, s1.y, s);
            s = ffma2(qC.x, s2.x, s);
            s = ffma2(qC.y, s2.y, s);
            s = ffma2(qD.x, s3.x, s);
            s = ffma2(qD.y, s3.y, s);
            float2 f = unpack2(s);
            qsp[i5] = f.x + f.y;
        }

        float ssum = 0.f;
#pragma unroll
        for (int tk = 0; tk < 3; tk++)
#pragma unroll
            for (int i5 = 0; i5 < 5; i5++) {
                int idx = tk * 5 + i5;
                float s = (a[idx] + qsp[i5]) * 0.25f;
                float e = valid ? fexp(s) : 0.f;
                a[idx] = e;
                ssum += e;
            }
        ssum += __shfl_xor_sync(0xffffffffu, ssum, 1);
        ssum += __shfl_xor_sync(0xffffffffu, ssum, 2);
        ssum += __shfl_xor_sync(0xffffffffu, ssum, 4);
        float rs = __fdividef(1.f, ssum);

        u64 acc[4][2];
#pragma unroll
        for (int q = 0; q < 4; q++) { acc[q][0] = 0ull; acc[q][1] = 0ull; }

#pragma unroll
        for (int tk = 0; tk < 3; tk++) {
#pragma unroll
            for (int i5 = 0; i5 < 5; i5++) {
                const int idx = tk * 5 + i5;
                const float* vrp = &Vr[slot[i5] * SLICE + (tk * 8 + rl) * KPAD + hoff + d4 * 4];
                ulonglong2 v = *(const ulonglong2*)vrp;
#pragma unroll
                for (int q = 0; q < 4; q++) {
                    float av = __shfl_sync(0xffffffffu, a[idx], (q << 3) | rl);
                    u64 aa = pack2(av, av);
                    acc[q][0] = ffma2(aa, v.x, acc[q][0]);
                    acc[q][1] = ffma2(aa, v.y, acc[q][1]);
                }
            }
        }
#pragma unroll
        for (int off = 1; off <= 4; off <<= 1) {
#pragma unroll
            for (int q = 0; q < 4; q++) {
                acc[q][0] = fadd2(acc[q][0], __shfl_xor_sync(0xffffffffu, acc[q][0], off));
                acc[q][1] = fadd2(acc[q][1], __shfl_xor_sync(0xffffffffu, acc[q][1], off));
            }
        }
        float rsw = __shfl_sync(0xffffffffu, rs, (lane & 7) * 8);
        if (rl < 4) {
            float2 lo = unpack2(acc[rl][0]);
            float2 hi = unpack2(acc[rl][1]);
            float o0 = lo.x * rsw, o1 = lo.y * rsw, o2 = hi.x * rsw, o3 = hi.y * rsw;
            uint32_t h0, l0, h1, l1;
            split2(o0, o1, h0, l0);
            split2(o2, o3, h1, l1);
            const size_t pi = ((size_t)(tq * HW_ + yq * W_ + x0 + rl) * CK + hoff + d4 * 4) >> 1;
            *(uint2*)&g_Ohi[pi] = make_uint2(h0, h1);
            *(uint2*)&g_Olo[pi] = make_uint2(l0, l1);
        }

        if (pf) asm volatile("cp.async.wait_group 0;");
        __syncthreads();
    }
}

// ---------------------------------------------------------------------------
extern "C" void kernel_launch(void* const* d_in, const int* in_sizes, int n_in,
                              void* d_out, int out_size)
{
    const float* x    = (const float*)d_in[0];
    const float* Wq   = (const float*)d_in[1];
    const float* Wk   = (const float*)d_in[2];
    const float* Wv   = (const float*)d_in[3];
    const float* Wo   = (const float*)d_in[4];
    const float* temp = (const float*)d_in[5];
    const float* sp   = (const float*)d_in[6];
    float* out = (float*)d_out;

    cudaFuncSetAttribute(qkv_mma_kernel, cudaFuncAttributeMaxDynamicSharedMemorySize, GEMM_SMEM);
    cudaFuncSetAttribute(outproj_mma_kernel, cudaFuncAttributeMaxDynamicSharedMemorySize, GEMM_SMEM);

    xprep_kernel<<<NT * 32 / 256, 256>>>(x);
    wprep_kernel<<<4, 256>>>(Wq, Wk, Wv, Wo);
    qkv_mma_kernel<<<dim3(NT / 128, 3), 256, GEMM_SMEM>>>(temp, sp);

    const size_t smem = (size_t)(2 * NSLOT * SLICE + 25 * KPAD) * sizeof(float);
    cudaFuncSetAttribute(attn_kernel, cudaFuncAttributeMaxDynamicSharedMemorySize, (int)smem);
    attn_kernel<<<dim3(XS, YB), 768, smem>>>(sp);

    outproj_mma_kernel<<<NT / 128, 256, GEMM_SMEM>>>(out);
}

// round 10
// speedup vs baseline: 1.2400x; 1.0840x over previous
#include <cuda_runtime.h>
#include <cuda_bf16.h>
#include <cstdint>

#define T_  3
#define H_  96
#define W_  96
#define C_  128
#define CK  128
#define NHEAD 8
#define DH  16
#define HW_ (H_*W_)
#define NT  (T_*HW_)        // 27648
#define QX  4
#define KPAD 132
#define SLICE (24*KPAD)
#define NSLOT 6
#define YSEG 16
#define XS (W_/QX)
#define YB (H_/YSEG)

typedef unsigned long long u64;

extern __shared__ char smraw[];

__device__ float g_Q[NT*CK];
__device__ float g_K[NT*CK];
__device__ float g_V[NT*CK];

// packed bf16 pairs (2 per uint32), row-major with 64 pairs per row of 128
__device__ uint32_t g_xhi[NT*64], g_xlo[NT*64];
__device__ uint32_t g_Ohi[NT*64], g_Olo[NT*64];
__device__ uint32_t g_Whi[4][128*64], g_Wlo[4][128*64];   // [k][n-pairs]

// ---------------- helpers ----------------
__device__ __forceinline__ u64 ffma2(u64 a, u64 b, u64 c) {
    u64 d; asm("fma.rn.f32x2 %0,%1,%2,%3;" : "=l"(d) : "l"(a), "l"(b), "l"(c)); return d;
}
__device__ __forceinline__ u64 fadd2(u64 a, u64 b) {
    u64 d; asm("add.rn.f32x2 %0,%1,%2;" : "=l"(d) : "l"(a), "l"(b)); return d;
}
__device__ __forceinline__ u64 pack2(float lo, float hi) {
    u64 d; asm("mov.b64 %0,{%1,%2};" : "=l"(d) : "f"(lo), "f"(hi)); return d;
}
__device__ __forceinline__ float2 unpack2(u64 v) {
    float2 r; asm("mov.b64 {%0,%1},%2;" : "=f"(r.x), "=f"(r.y) : "l"(v)); return r;
}
__device__ __forceinline__ void cp16(uint32_t dst, const void* src) {
    asm volatile("cp.async.cg.shared.global [%0], [%1], 16;" :: "r"(dst), "l"(src));
}
__device__ __forceinline__ void split2(float x0, float x1, uint32_t& h, uint32_t& l) {
    __nv_bfloat16 h0 = __float2bfloat16(x0);
    __nv_bfloat16 h1 = __float2bfloat16(x1);
    __nv_bfloat16 l0 = __float2bfloat16(x0 - __bfloat162float(h0));
    __nv_bfloat16 l1 = __float2bfloat16(x1 - __bfloat162float(h1));
    h = ((uint32_t)__bfloat16_as_ushort(h1) << 16) | __bfloat16_as_ushort(h0);
    l = ((uint32_t)__bfloat16_as_ushort(l1) << 16) | __bfloat16_as_ushort(l0);
}
// e = 2^t (hardware approx, ~2^-22 rel err)
__device__ __forceinline__ float ex2(float t) {
    float e; asm("ex2.approx.f32 %0, %1;" : "=f"(e) : "f"(t)); return e;
}

// ---------------- mma helpers ----------------
__device__ __forceinline__ void ldsm_x4(uint32_t* a, uint32_t addr) {
    asm volatile("ldmatrix.sync.aligned.m8n8.x4.shared.b16 {%0,%1,%2,%3}, [%4];"
                 : "=r"(a[0]), "=r"(a[1]), "=r"(a[2]), "=r"(a[3]) : "r"(addr));
}
__device__ __forceinline__ void ldsm_x2t(uint32_t* b, uint32_t addr) {
    asm volatile("ldmatrix.sync.aligned.m8n8.x2.trans.shared.b16 {%0,%1}, [%2];"
                 : "=r"(b[0]), "=r"(b[1]) : "r"(addr));
}
__device__ __forceinline__ void mma16816(float* c, const uint32_t* a, const uint32_t* b) {
    asm volatile(
        "mma.sync.aligned.m16n8k16.row.col.f32.bf16.bf16.f32 "
        "{%0,%1,%2,%3}, {%4,%5,%6,%7}, {%8,%9}, {%0,%1,%2,%3};"
        : "+f"(c[0]), "+f"(c[1]), "+f"(c[2]), "+f"(c[3])
        : "r"(a[0]), "r"(a[1]), "r"(a[2]), "r"(a[3]), "r"(b[0]), "r"(b[1]));
}

// smem: 4 tiles of 128 rows x 272 bytes (136 bf16 stride)
#define BROW 272
#define TILE_B (128*BROW)       // 34816
#define AHI_OFF 0
#define ALO_OFF TILE_B
#define BHI_OFF (2*TILE_B)
#define BLO_OFF (3*TILE_B)
#define GEMM_SMEM (4*TILE_B)    // 139264

// ---------------------------------------------------------------------------
// prep kernels
// ---------------------------------------------------------------------------
__global__ __launch_bounds__(256) void xprep_kernel(const float* __restrict__ x) {
    int i = blockIdx.x * 256 + threadIdx.x;      // one float4 = 2 pairs
    float4 v = *(const float4*)&x[(size_t)i * 4];
    uint32_t h0, l0, h1, l1;
    split2(v.x, v.y, h0, l0);
    split2(v.z, v.w, h1, l1);
    *(uint2*)&g_xhi[i * 2] = make_uint2(h0, h1);
    *(uint2*)&g_xlo[i * 2] = make_uint2(l0, l1);
}

__global__ __launch_bounds__(256) void wprep_kernel(
    const float* __restrict__ Wq, const float* __restrict__ Wk,
    const float* __restrict__ Wv, const float* __restrict__ Wo)
{
    const int mat = blockIdx.x;
    const float* Wsrc = (mat == 0) ? Wq : (mat == 1) ? Wk : (mat == 2) ? Wv : Wo;
    for (int p = threadIdx.x; p < 128 * 64; p += 256) {
        float2 v = *(const float2*)&Wsrc[(size_t)p * 2];   // row-major [k][n]
        uint32_t h, l;
        split2(v.x, v.y, h, l);
        g_Whi[mat][p] = h;
        g_Wlo[mat][p] = l;
    }
}

// ---------------------------------------------------------------------------
// Shared MMA body: 2-group cp.async fill (hi tiles first), c[2][8][4] per warp.
// ---------------------------------------------------------------------------
__device__ __forceinline__ void mma_body(
    const uint32_t* __restrict__ Ahi, const uint32_t* __restrict__ Alo,
    int mat, int m0, float c[2][8][4])
{
    const int tid  = threadIdx.x;
    const int w    = tid >> 5;
    const int lane = tid & 31;
    const uint32_t sb = (uint32_t)__cvta_generic_to_shared(smraw);

    // group 1: Ahi + Bhi (needed for pass 0)
#pragma unroll
    for (int it = 0; it < 8; it++) {
        int i = tid + it * 256;
        int r = i >> 4, ch = i & 15;
        uint32_t d = (uint32_t)(r * BROW + ch * 16);
        cp16(sb + AHI_OFF + d, (const char*)Ahi + ((size_t)(m0 + r) * 64 + ch * 4) * 4);
        cp16(sb + BHI_OFF + d, (const char*)&g_Whi[mat][r * 64 + ch * 4]);
    }
    asm volatile("cp.async.commit_group;");
    // group 2: Alo + Blo
#pragma unroll
    for (int it = 0; it < 8; it++) {
        int i = tid + it * 256;
        int r = i >> 4, ch = i & 15;
        uint32_t d = (uint32_t)(r * BROW + ch * 16);
        cp16(sb + ALO_OFF + d, (const char*)Alo + ((size_t)(m0 + r) * 64 + ch * 4) * 4);
        cp16(sb + BLO_OFF + d, (const char*)&g_Wlo[mat][r * 64 + ch * 4]);
    }
    asm volatile("cp.async.commit_group;");

#pragma unroll
    for (int mt = 0; mt < 2; mt++)
#pragma unroll
        for (int nt = 0; nt < 8; nt++)
#pragma unroll
            for (int j = 0; j < 4; j++) c[mt][nt][j] = 0.f;

    const int wm = w & 3, wn = w >> 2;
    const uint32_t aBase = sb + (uint32_t)((wm * 32 + (lane & 15)) * BROW + (lane >> 4) * 16);
    const uint32_t bBase = sb + (uint32_t)((lane & 15) * BROW + wn * 128);

    const uint32_t aOffP[3] = {AHI_OFF, AHI_OFF, ALO_OFF};
    const uint32_t bOffP[3] = {BHI_OFF, BLO_OFF, BHI_OFF};

    asm volatile("cp.async.wait_group 1;");   // group 1 done
    __syncthreads();

#pragma unroll
    for (int pass = 0; pass < 3; pass++) {
        if (pass == 1) {
            asm volatile("cp.async.wait_group 0;");   // group 2 done
            __syncthreads();
        }
        const uint32_t aT = aBase + aOffP[pass];
        const uint32_t bT = bBase + bOffP[pass];
#pragma unroll
        for (int k8 = 0; k8 < 8; k8++) {
            uint32_t a[2][4], b[8][2];
#pragma unroll
            for (int mt = 0; mt < 2; mt++)
                ldsm_x4(a[mt], aT + (uint32_t)(mt * 16 * BROW + k8 * 32));
#pragma unroll
            for (int nt = 0; nt < 8; nt++)
                ldsm_x2t(b[nt], bT + (uint32_t)(k8 * 16 * BROW + nt * 16));
#pragma unroll
            for (int mt = 0; mt < 2; mt++)
#pragma unroll
                for (int nt = 0; nt < 8; nt++)
                    mma16816(c[mt][nt], a[mt], b[nt]);
        }
    }
}

// ---------------------------------------------------------------------------
// Kernel: QKV via mma.sync + embedding epilogue. grid (216, 3)
// ---------------------------------------------------------------------------
__global__ __launch_bounds__(256, 1) void qkv_mma_kernel(
    const float* __restrict__ temp_emb, const float* __restrict__ sp_emb)
{
    const int mat = blockIdx.y;
    float* dst = (mat == 0) ? g_Q : (mat == 1) ? g_K : g_V;
    const int m0 = blockIdx.x * 128;

    float c[2][8][4];
    mma_body(g_xhi, g_xlo, mat, m0, c);

    const int w = threadIdx.x >> 5, lane = threadIdx.x & 31;
    const int wm = w & 3, wn = w >> 2;
#pragma unroll
    for (int mt = 0; mt < 2; mt++) {
#pragma unroll
        for (int rh = 0; rh < 2; rh++) {
            const int n   = m0 + wm * 32 + mt * 16 + (lane >> 2) + rh * 8;
            const int t   = n / HW_;
            const int rem = n % HW_;
            int qidx = 0;
            if (mat == 0) {
                const int yq = rem / W_, xq = rem % W_;
                const int yc = min(max(yq, 2), H_ - 3);
                const int xc = min(max(xq, 2), W_ - 3);
                qidx = (yq - yc + 2) * 5 + (xq - xc + 2);
            }
#pragma unroll
            for (int nt = 0; nt < 8; nt++) {
                const int col = wn * 64 + nt * 8 + 2 * (lane & 3);
                float v0 = c[mt][nt][rh * 2 + 0];
                float v1 = c[mt][nt][rh * 2 + 1];
                if (mat <= 1) {
                    v0 += temp_emb[t * CK + col];
                    v1 += temp_emb[t * CK + col + 1];
                }
                if (mat == 0) {
                    v0 += sp_emb[qidx * CK + col];
                    v1 += sp_emb[qidx * CK + col + 1];
                }
                *(float2*)&dst[(size_t)n * CK + col] = make_float2(v0, v1);
            }
        }
    }
}

// ---------------------------------------------------------------------------
// Kernel: output projection via mma.sync + transposed writeout. grid 216
// ---------------------------------------------------------------------------
__global__ __launch_bounds__(256, 1) void outproj_mma_kernel(float* __restrict__ out)
{
    const int m0 = blockIdx.x * 128;

    float c[2][8][4];
    mma_body(g_Ohi, g_Olo, 3, m0, c);

    const int w = threadIdx.x >> 5, lane = threadIdx.x & 31;
    const int wm = w & 3, wn = w >> 2;
#pragma unroll
    for (int mt = 0; mt < 2; mt++) {
#pragma unroll
        for (int rh = 0; rh < 2; rh++) {
            const int n   = m0 + wm * 32 + mt * 16 + (lane >> 2) + rh * 8;
            const int t   = n / HW_;
            const int rem = n % HW_;
            const size_t ob = (size_t)rem * (T_ * C_) + t * C_;
#pragma unroll
            for (int nt = 0; nt < 8; nt++) {
                const int col = wn * 64 + nt * 8 + 2 * (lane & 3);
                *(float2*)&out[ob + col] =
                    make_float2(c[mt][nt][rh * 2 + 0], c[mt][nt][rh * 2 + 1]);
            }
        }
    }
}

// ---------------------------------------------------------------------------
// Kernel: attention, rolling-window persistent blocks. exp via ex2.approx.
// ---------------------------------------------------------------------------
__global__ __launch_bounds__(768) void attn_kernel(const float* __restrict__ sp_emb)
{
    float* sm  = (float*)smraw;
    float* Kr  = sm;
    float* Vr  = Kr + NSLOT * SLICE;
    float* SPs = Vr + NSLOT * SLICE;

    const uint32_t sbase = (uint32_t)__cvta_generic_to_shared(sm);
    const uint32_t Kb  = sbase;
    const uint32_t Vb  = sbase + NSLOT * SLICE * 4;
    const uint32_t SPb = Vb + NSLOT * SLICE * 4;

    const int x0  = blockIdx.x * QX;
    const int y0  = blockIdx.y * YSEG;
    const int tid = threadIdx.x;
    const int xbase = min(max(x0, 2), W_ - 3) - 2;

    const int srow = tid >> 5;
    const int sc4  = (tid & 31) * 4;
    const int st   = srow >> 3;
    const int scol = min(xbase + (srow & 7), W_ - 1);
    const size_t sgbase = (size_t)(st * HW_ + scol) * CK + sc4;
    const uint32_t ssoff = (srow * KPAD + sc4) * 4;

    for (int i = tid; i < 25 * 32; i += 768) {
        int p = i >> 5, c4 = (i & 31) * 4;
        cp16(SPb + (uint32_t)(p * KPAD + c4) * 4, &sp_emb[p * 128 + c4]);
    }
    const int yc0 = min(max(y0, 2), H_ - 3);
#pragma unroll
    for (int r = 0; r < 5; r++) {
        const int yr = yc0 - 2 + r;
        const uint32_t so = (uint32_t)((yr % NSLOT) * SLICE * 4) + ssoff;
        const size_t g = sgbase + (size_t)yr * W_ * CK;
        cp16(Kb + so, &g_K[g]);
        cp16(Vb + so, &g_V[g]);
    }
    asm volatile("cp.async.commit_group;");
    asm volatile("cp.async.wait_group 0;");
    __syncthreads();
    int loaded_max = yc0 + 2;

    const int lane = tid & 31;
    const int w    = tid >> 5;
    const int tq   = w / NHEAD;
    const int h    = w % NHEAD;
    const int hoff = h * DH;

    const int qx  = lane >> 3;
    const int rl  = lane & 7;
    const int xoffq = min(max(x0 + qx, 2), W_ - 3) - 2 - xbase;
    const int kxr   = rl - xoffq;
    const bool valid = (kxr >= 0) && (kxr <= 4);
    const int kxrc  = min(max(kxr, 0), 4);
    const int d4 = lane >> 3;

    const float L2S = 0.36067376022224085f;   // 0.25 * log2(e)

    for (int yq = y0; yq < y0 + YSEG; yq++) {
        const int yc = min(max(yq, 2), H_ - 3);

        const int need_next = min(max(yq + 1, 2), H_ - 3) + 2;
        const bool pf = (yq + 1 < y0 + YSEG) && (need_next > loaded_max);
        if (pf) {
            const uint32_t so = (uint32_t)((need_next % NSLOT) * SLICE * 4) + ssoff;
            const size_t g = sgbase + (size_t)need_next * W_ * CK;
            cp16(Kb + so, &g_K[g]);
            cp16(Vb + so, &g_V[g]);
            asm volatile("cp.async.commit_group;");
            loaded_max = need_next;
        }

        int slot[5];
        {
            int s0 = (yc - 2) % NSLOT;
#pragma unroll
            for (int i5 = 0; i5 < 5; i5++) {
                slot[i5] = s0;
                s0 = (s0 + 1 == NSLOT) ? 0 : s0 + 1;
            }
        }

        const float* qp = &g_Q[(size_t)(tq * HW_ + yq * W_ + x0 + qx) * CK + hoff];
        ulonglong2 qA = *(const ulonglong2*)&qp[0];
        ulonglong2 qB = *(const ulonglong2*)&qp[4];
        ulonglong2 qC = *(const ulonglong2*)&qp[8];
        ulonglong2 qD = *(const ulonglong2*)&qp[12];

        float a[15];
#pragma unroll
        for (int tk = 0; tk < 3; tk++) {
#pragma unroll
            for (int i5 = 0; i5 < 5; i5++) {
                const float* kr = &Kr[slot[i5] * SLICE + (tk * 8 + rl) * KPAD + hoff];
                ulonglong2 k0 = *(const ulonglong2*)&kr[0];
                ulonglong2 k1 = *(const ulonglong2*)&kr[4];
                ulonglong2 k2 = *(const ulonglong2*)&kr[8];
                ulonglong2 k3 = *(const ulonglong2*)&kr[12];
                u64 s = ffma2(qA.x, k0.x, 0ull);
                s = ffma2(qA.y, k0.y, s);
                s = ffma2(qB.x, k1.x, s);
                s = ffma2(qB.y, k1.y, s);
                s = ffma2(qC.x, k2.x, s);
                s = ffma2(qC.y, k2.y, s);
                s = ffma2(qD.x, k3.x, s);
                s = ffma2(qD.y, k3.y, s);
                float2 f = unpack2(s);
                a[tk * 5 + i5] = f.x + f.y;
            }
        }

        float qsp[5];
#pragma unroll
        for (int i5 = 0; i5 < 5; i5++) {
            const float* sp = &SPs[(i5 * 5 + kxrc) * KPAD + hoff];
            ulonglong2 s0 = *(const ulonglong2*)&sp[0];
            ulonglong2 s1 = *(const ulonglong2*)&sp[4];
            ulonglong2 s2 = *(const ulonglong2*)&sp[8];
            ulonglong2 s3 = *(const ulonglong2*)&sp[12];
            u64 s = ffma2(qA.x, s0.x, 0ull);
            s = ffma2(qA.y, s0.y, s);
            s = ffma2(qB.x, s1.x, s);
            s = ffma2(qB.y, s1.y, s);
            s = ffma2(qC.x, s2.x, s);
            s = ffma2(qC.y, s2.y, s);
            s = ffma2(qD.x, s3.x, s);
            s = ffma2(qD.y, s3.y, s);
            float2 f = unpack2(s);
            qsp[i5] = f.x + f.y;
        }

        float ssum = 0.f;
#pragma unroll
        for (int tk = 0; tk < 3; tk++)
#pragma unroll
            for (int i5 = 0; i5 < 5; i5++) {
                int idx = tk * 5 + i5;
                float e = ex2((a[idx] + qsp[i5]) * L2S);
                e = valid ? e : 0.f;
                a[idx] = e;
                ssum += e;
            }
        ssum += __shfl_xor_sync(0xffffffffu, ssum, 1);
        ssum += __shfl_xor_sync(0xffffffffu, ssum, 2);
        ssum += __shfl_xor_sync(0xffffffffu, ssum, 4);
        float rs = __fdividef(1.f, ssum);

        u64 acc[4][2];
#pragma unroll
        for (int q = 0; q < 4; q++) { acc[q][0] = 0ull; acc[q][1] = 0ull; }

#pragma unroll
        for (int tk = 0; tk < 3; tk++) {
#pragma unroll
            for (int i5 = 0; i5 < 5; i5++) {
                const int idx = tk * 5 + i5;
                const float* vrp = &Vr[slot[i5] * SLICE + (tk * 8 + rl) * KPAD + hoff + d4 * 4];
                ulonglong2 v = *(const ulonglong2*)vrp;
#pragma unroll
                for (int q = 0; q < 4; q++) {
                    float av = __shfl_sync(0xffffffffu, a[idx], (q << 3) | rl);
                    u64 aa = pack2(av, av);
                    acc[q][0] = ffma2(aa, v.x, acc[q][0]);
                    acc[q][1] = ffma2(aa, v.y, acc[q][1]);
                }
            }
        }
#pragma unroll
        for (int off = 1; off <= 4; off <<= 1) {
#pragma unroll
            for (int q = 0; q < 4; q++) {
                acc[q][0] = fadd2(acc[q][0], __shfl_xor_sync(0xffffffffu, acc[q][0], off));
                acc[q][1] = fadd2(acc[q][1], __shfl_xor_sync(0xffffffffu, acc[q][1], off));
            }
        }
        float rsw = __shfl_sync(0xffffffffu, rs, (lane & 7) * 8);
        if (rl < 4) {
            float2 lo = unpack2(acc[rl][0]);
            float2 hi = unpack2(acc[rl][1]);
            float o0 = lo.x * rsw, o1 = lo.y * rsw, o2 = hi.x * rsw, o3 = hi.y * rsw;
            uint32_t h0, l0, h1, l1;
            split2(o0, o1, h0, l0);
            split2(o2, o3, h1, l1);
            const size_t pi = ((size_t)(tq * HW_ + yq * W_ + x0 + rl) * CK + hoff + d4 * 4) >> 1;
            *(uint2*)&g_Ohi[pi] = make_uint2(h0, h1);
            *(uint2*)&g_Olo[pi] = make_uint2(l0, l1);
        }

        if (pf) asm volatile("cp.async.wait_group 0;");
        __syncthreads();
    }
}

// ---------------------------------------------------------------------------
extern "C" void kernel_launch(void* const* d_in, const int* in_sizes, int n_in,
                              void* d_out, int out_size)
{
    const float* x    = (const float*)d_in[0];
    const float* Wq   = (const float*)d_in[1];
    const float* Wk   = (const float*)d_in[2];
    const float* Wv   = (const float*)d_in[3];
    const float* Wo   = (const float*)d_in[4];
    const float* temp = (const float*)d_in[5];
    const float* sp   = (const float*)d_in[6];
    float* out = (float*)d_out;

    cudaFuncSetAttribute(qkv_mma_kernel, cudaFuncAttributeMaxDynamicSharedMemorySize, GEMM_SMEM);
    cudaFuncSetAttribute(outproj_mma_kernel, cudaFuncAttributeMaxDynamicSharedMemorySize, GEMM_SMEM);

    xprep_kernel<<<NT * 32 / 256, 256>>>(x);
    wprep_kernel<<<4, 256>>>(Wq, Wk, Wv, Wo);
    qkv_mma_kernel<<<dim3(NT / 128, 3), 256, GEMM_SMEM>>>(temp, sp);

    const size_t smem = (size_t)(2 * NSLOT * SLICE + 25 * KPAD) * sizeof(float);
    cudaFuncSetAttribute(attn_kernel, cudaFuncAttributeMaxDynamicSharedMemorySize, (int)smem);
    attn_kernel<<<dim3(XS, YB), 768, smem>>>(sp);

    outproj_mma_kernel<<<NT / 128, 256, GEMM_SMEM>>>(out);
}

// round 11
// speedup vs baseline: 1.4437x; 1.1643x over previous
#include <cuda_runtime.h>
#include <cuda_bf16.h>
#include <cuda_fp16.h>
#include <cstdint>

#define T_  3
#define H_  96
#define W_  96
#define C_  128
#define CK  128
#define NHEAD 8
#define DH  16
#define HW_ (H_*W_)
#define NT  (T_*HW_)        // 27648
#define QX  4
#define YSEG 16
#define XS (W_/QX)
#define YB (H_/YSEG)
#define NSLOT 6

// fp16 K/V smem layout: row = 128 halves = 256B data + 16B pad
#define HROW 272
#define SLICEB (24*HROW)    // 6528 bytes per y-slice per array
#define ATTN_SMEM (12*SLICEB + 25*HROW)   // 85136

typedef unsigned long long u64;

extern __shared__ char smraw[];

__device__ float g_Q[NT*CK];

// fp16 packed pairs (half2 per uint32): 64 per row of 128
__device__ uint32_t g_Kh[NT*64], g_Vh[NT*64], g_sph[25*64];

// bf16 split pairs for MMA GEMMs
__device__ uint32_t g_xhi[NT*64], g_xlo[NT*64];
__device__ uint32_t g_Ohi[NT*64], g_Olo[NT*64];
__device__ uint32_t g_Whi[4][128*64], g_Wlo[4][128*64];

// ---------------- helpers ----------------
__device__ __forceinline__ u64 ffma2(u64 a, u64 b, u64 c) {
    u64 d; asm("fma.rn.f32x2 %0,%1,%2,%3;" : "=l"(d) : "l"(a), "l"(b), "l"(c)); return d;
}
__device__ __forceinline__ u64 fadd2(u64 a, u64 b) {
    u64 d; asm("add.rn.f32x2 %0,%1,%2;" : "=l"(d) : "l"(a), "l"(b)); return d;
}
__device__ __forceinline__ u64 pack2(float lo, float hi) {
    u64 d; asm("mov.b64 %0,{%1,%2};" : "=l"(d) : "f"(lo), "f"(hi)); return d;
}
__device__ __forceinline__ float2 unpack2(u64 v) {
    float2 r; asm("mov.b64 {%0,%1},%2;" : "=f"(r.x), "=f"(r.y) : "l"(v)); return r;
}
__device__ __forceinline__ void cp16(uint32_t dst, const void* src) {
    asm volatile("cp.async.cg.shared.global [%0], [%1], 16;" :: "r"(dst), "l"(src));
}
__device__ __forceinline__ void split2(float x0, float x1, uint32_t& h, uint32_t& l) {
    __nv_bfloat16 h0 = __float2bfloat16(x0);
    __nv_bfloat16 h1 = __float2bfloat16(x1);
    __nv_bfloat16 l0 = __float2bfloat16(x0 - __bfloat162float(h0));
    __nv_bfloat16 l1 = __float2bfloat16(x1 - __bfloat162float(h1));
    h = ((uint32_t)__bfloat16_as_ushort(h1) << 16) | __bfloat16_as_ushort(h0);
    l = ((uint32_t)__bfloat16_as_ushort(l1) << 16) | __bfloat16_as_ushort(l0);
}
__device__ __forceinline__ float ex2(float t) {
    float e; asm("ex2.approx.f32 %0, %1;" : "=f"(e) : "f"(t)); return e;
}
#define H2(u) (*reinterpret_cast<const __half2*>(&(u)))

// ---------------- mma helpers ----------------
__device__ __forceinline__ void ldsm_x4(uint32_t* a, uint32_t addr) {
    asm volatile("ldmatrix.sync.aligned.m8n8.x4.shared.b16 {%0,%1,%2,%3}, [%4];"
                 : "=r"(a[0]), "=r"(a[1]), "=r"(a[2]), "=r"(a[3]) : "r"(addr));
}
__device__ __forceinline__ void ldsm_x2t(uint32_t* b, uint32_t addr) {
    asm volatile("ldmatrix.sync.aligned.m8n8.x2.trans.shared.b16 {%0,%1}, [%2];"
                 : "=r"(b[0]), "=r"(b[1]) : "r"(addr));
}
__device__ __forceinline__ void mma16816(float* c, const uint32_t* a, const uint32_t* b) {
    asm volatile(
        "mma.sync.aligned.m16n8k16.row.col.f32.bf16.bf16.f32 "
        "{%0,%1,%2,%3}, {%4,%5,%6,%7}, {%8,%9}, {%0,%1,%2,%3};"
        : "+f"(c[0]), "+f"(c[1]), "+f"(c[2]), "+f"(c[3])
        : "r"(a[0]), "r"(a[1]), "r"(a[2]), "r"(a[3]), "r"(b[0]), "r"(b[1]));
}

#define BROW 272
#define TILE_B (128*BROW)
#define AHI_OFF 0
#define ALO_OFF TILE_B
#define BHI_OFF (2*TILE_B)
#define BLO_OFF (3*TILE_B)
#define GEMM_SMEM (4*TILE_B)

// ---------------------------------------------------------------------------
// prep kernels
// ---------------------------------------------------------------------------
__global__ __launch_bounds__(256) void xprep_kernel(const float* __restrict__ x) {
    int i = blockIdx.x * 256 + threadIdx.x;
    float4 v = *(const float4*)&x[(size_t)i * 4];
    uint32_t h0, l0, h1, l1;
    split2(v.x, v.y, h0, l0);
    split2(v.z, v.w, h1, l1);
    *(uint2*)&g_xhi[i * 2] = make_uint2(h0, h1);
    *(uint2*)&g_xlo[i * 2] = make_uint2(l0, l1);
}

__global__ __launch_bounds__(256) void wprep_kernel(
    const float* __restrict__ Wq, const float* __restrict__ Wk,
    const float* __restrict__ Wv, const float* __restrict__ Wo,
    const float* __restrict__ sp_emb)
{
    const int mat = blockIdx.x;
    if (mat == 4) {   // sp_emb -> fp16 pairs
        for (int i = threadIdx.x; i < 25 * 64; i += 256) {
            float2 v = *(const float2*)&sp_emb[(size_t)i * 2];
            __half2 hv = __float22half2_rn(v);
            g_sph[i] = *(uint32_t*)&hv;
        }
        return;
    }
    const float* Wsrc = (mat == 0) ? Wq : (mat == 1) ? Wk : (mat == 2) ? Wv : Wo;
    for (int p = threadIdx.x; p < 128 * 64; p += 256) {
        float2 v = *(const float2*)&Wsrc[(size_t)p * 2];
        uint32_t h, l;
        split2(v.x, v.y, h, l);
        g_Whi[mat][p] = h;
        g_Wlo[mat][p] = l;
    }
}

// ---------------------------------------------------------------------------
// Shared MMA body (R10): 2-group cp.async fill, c[2][8][4] per warp.
// ---------------------------------------------------------------------------
__device__ __forceinline__ void mma_body(
    const uint32_t* __restrict__ Ahi, const uint32_t* __restrict__ Alo,
    int mat, int m0, float c[2][8][4])
{
    const int tid  = threadIdx.x;
    const int w    = tid >> 5;
    const int lane = tid & 31;
    const uint32_t sb = (uint32_t)__cvta_generic_to_shared(smraw);

#pragma unroll
    for (int it = 0; it < 8; it++) {
        int i = tid + it * 256;
        int r = i >> 4, ch = i & 15;
        uint32_t d = (uint32_t)(r * BROW + ch * 16);
        cp16(sb + AHI_OFF + d, (const char*)Ahi + ((size_t)(m0 + r) * 64 + ch * 4) * 4);
        cp16(sb + BHI_OFF + d, (const char*)&g_Whi[mat][r * 64 + ch * 4]);
    }
    asm volatile("cp.async.commit_group;");
#pragma unroll
    for (int it = 0; it < 8; it++) {
        int i = tid + it * 256;
        int r = i >> 4, ch = i & 15;
        uint32_t d = (uint32_t)(r * BROW + ch * 16);
        cp16(sb + ALO_OFF + d, (const char*)Alo + ((size_t)(m0 + r) * 64 + ch * 4) * 4);
        cp16(sb + BLO_OFF + d, (const char*)&g_Wlo[mat][r * 64 + ch * 4]);
    }
    asm volatile("cp.async.commit_group;");

#pragma unroll
    for (int mt = 0; mt < 2; mt++)
#pragma unroll
        for (int nt = 0; nt < 8; nt++)
#pragma unroll
            for (int j = 0; j < 4; j++) c[mt][nt][j] = 0.f;

    const int wm = w & 3, wn = w >> 2;
    const uint32_t aBase = sb + (uint32_t)((wm * 32 + (lane & 15)) * BROW + (lane >> 4) * 16);
    const uint32_t bBase = sb + (uint32_t)((lane & 15) * BROW + wn * 128);

    const uint32_t aOffP[3] = {AHI_OFF, AHI_OFF, ALO_OFF};
    const uint32_t bOffP[3] = {BHI_OFF, BLO_OFF, BHI_OFF};

    asm volatile("cp.async.wait_group 1;");
    __syncthreads();

#pragma unroll
    for (int pass = 0; pass < 3; pass++) {
        if (pass == 1) {
            asm volatile("cp.async.wait_group 0;");
            __syncthreads();
        }
        const uint32_t aT = aBase + aOffP[pass];
        const uint32_t bT = bBase + bOffP[pass];
#pragma unroll
        for (int k8 = 0; k8 < 8; k8++) {
            uint32_t a[2][4], b[8][2];
#pragma unroll
            for (int mt = 0; mt < 2; mt++)
                ldsm_x4(a[mt], aT + (uint32_t)(mt * 16 * BROW + k8 * 32));
#pragma unroll
            for (int nt = 0; nt < 8; nt++)
                ldsm_x2t(b[nt], bT + (uint32_t)(k8 * 16 * BROW + nt * 16));
#pragma unroll
            for (int mt = 0; mt < 2; mt++)
#pragma unroll
                for (int nt = 0; nt < 8; nt++)
                    mma16816(c[mt][nt], a[mt], b[nt]);
        }
    }
}

// ---------------------------------------------------------------------------
// Kernel: QKV via mma.sync. Q -> fp32; K,V -> fp16 half2 pairs.
// ---------------------------------------------------------------------------
__global__ __launch_bounds__(256, 1) void qkv_mma_kernel(
    const float* __restrict__ temp_emb, const float* __restrict__ sp_emb)
{
    const int mat = blockIdx.y;
    const int m0 = blockIdx.x * 128;

    float c[2][8][4];
    mma_body(g_xhi, g_xlo, mat, m0, c);

    const int w = threadIdx.x >> 5, lane = threadIdx.x & 31;
    const int wm = w & 3, wn = w >> 2;
    uint32_t* dsth = (mat == 1) ? g_Kh : g_Vh;
#pragma unroll
    for (int mt = 0; mt < 2; mt++) {
#pragma unroll
        for (int rh = 0; rh < 2; rh++) {
            const int n   = m0 + wm * 32 + mt * 16 + (lane >> 2) + rh * 8;
            const int t   = n / HW_;
            const int rem = n % HW_;
            int qidx = 0;
            if (mat == 0) {
                const int yq = rem / W_, xq = rem % W_;
                const int yc = min(max(yq, 2), H_ - 3);
                const int xc = min(max(xq, 2), W_ - 3);
                qidx = (yq - yc + 2) * 5 + (xq - xc + 2);
            }
#pragma unroll
            for (int nt = 0; nt < 8; nt++) {
                const int col = wn * 64 + nt * 8 + 2 * (lane & 3);
                float v0 = c[mt][nt][rh * 2 + 0];
                float v1 = c[mt][nt][rh * 2 + 1];
                if (mat <= 1) {
                    v0 += temp_emb[t * CK + col];
                    v1 += temp_emb[t * CK + col + 1];
                }
                if (mat == 0) {
                    v0 += sp_emb[qidx * CK + col];
                    v1 += sp_emb[qidx * CK + col + 1];
                    *(float2*)&g_Q[(size_t)n * CK + col] = make_float2(v0, v1);
                } else {
                    __half2 hv = __float22half2_rn(make_float2(v0, v1));
                    dsth[(size_t)n * 64 + (col >> 1)] = *(uint32_t*)&hv;
                }
            }
        }
    }
}

// ---------------------------------------------------------------------------
// Kernel: output projection via mma.sync + transposed writeout.
// ---------------------------------------------------------------------------
__global__ __launch_bounds__(256, 1) void outproj_mma_kernel(float* __restrict__ out)
{
    const int m0 = blockIdx.x * 128;

    float c[2][8][4];
    mma_body(g_Ohi, g_Olo, 3, m0, c);

    const int w = threadIdx.x >> 5, lane = threadIdx.x & 31;
    const int wm = w & 3, wn = w >> 2;
#pragma unroll
    for (int mt = 0; mt < 2; mt++) {
#pragma unroll
        for (int rh = 0; rh < 2; rh++) {
            const int n   = m0 + wm * 32 + mt * 16 + (lane >> 2) + rh * 8;
            const int t   = n / HW_;
            const int rem = n % HW_;
            const size_t ob = (size_t)rem * (T_ * C_) + t * C_;
#pragma unroll
            for (int nt = 0; nt < 8; nt++) {
                const int col = wn * 64 + nt * 8 + 2 * (lane & 3);
                *(float2*)&out[ob + col] =
                    make_float2(c[mt][nt][rh * 2 + 0], c[mt][nt][rh * 2 + 1]);
            }
        }
    }
}

// ---------------------------------------------------------------------------
// Kernel: attention, rolling-window persistent blocks, fp16 K/V/sp in smem.
// ---------------------------------------------------------------------------
__global__ __launch_bounds__(768) void attn_kernel()
{
    char* Krh = smraw;                       // 6 x SLICEB
    char* Vrh = smraw + 6 * SLICEB;          // 6 x SLICEB
    char* SPh = smraw + 12 * SLICEB;         // 25 x HROW

    const uint32_t sbase = (uint32_t)__cvta_generic_to_shared(smraw);
    const uint32_t Kb0 = sbase;
    const uint32_t Vb0 = sbase + 6 * SLICEB;
    const uint32_t SPb = sbase + 12 * SLICEB;

    const int x0  = blockIdx.x * QX;
    const int y0  = blockIdx.y * YSEG;
    const int tid = threadIdx.x;
    const int xbase = min(max(x0, 2), W_ - 3) - 2;

    // per-thread slice-gather coords: 384 chunks per array (24 rows x 16)
    const bool isV = tid >= 384;
    const int j    = isV ? tid - 384 : tid;
    const int grow = j >> 4;                 // 0..23 = t*8 + kx
    const int gch  = j & 15;
    const int gt   = grow >> 3;
    const int gcol = min(xbase + (grow & 7), W_ - 1);
    const size_t sgbase = (size_t)(gt * HW_ + gcol) * 64 + gch * 4;   // uint32 idx
    const uint32_t ssoff = (uint32_t)(grow * HROW + gch * 16);
    const uint32_t* gsrc = isV ? g_Vh : g_Kh;
    const uint32_t sdstb = isV ? Vb0 : Kb0;

    // prologue: sp_emb + initial 5 slices
    if (tid < 400) {
        int r = tid >> 4, ch = tid & 15;
        cp16(SPb + (uint32_t)(r * HROW + ch * 16), &g_sph[r * 64 + ch * 4]);
    }
    const int yc0 = min(max(y0, 2), H_ - 3);
#pragma unroll
    for (int r = 0; r < 5; r++) {
        const int yr = yc0 - 2 + r;
        cp16(sdstb + (uint32_t)((yr % NSLOT) * SLICEB) + ssoff,
             &gsrc[sgbase + (size_t)yr * W_ * 64]);
    }
    asm volatile("cp.async.commit_group;");
    asm volatile("cp.async.wait_group 0;");
    __syncthreads();
    int loaded_max = yc0 + 2;

    const int lane = tid & 31;
    const int w    = tid >> 5;
    const int tq   = w / NHEAD;
    const int h    = w % NHEAD;
    const int hoff = h * DH;        // fp32 Q offset
    const int hb   = h << 5;        // byte offset within fp16 row

    const int qx  = lane >> 3;
    const int rl  = lane & 7;
    const int xoffq = min(max(x0 + qx, 2), W_ - 3) - 2 - xbase;
    const int kxr   = rl - xoffq;
    const bool valid = (kxr >= 0) && (kxr <= 4);
    const int kxrc  = min(max(kxr, 0), 4);
    const int d4 = lane >> 3;

    const float L2S = 0.36067376022224085f;   // 0.25 * log2(e)

    for (int yq = y0; yq < y0 + YSEG; yq++) {
        const int yc = min(max(yq, 2), H_ - 3);

        const int need_next = min(max(yq + 1, 2), H_ - 3) + 2;
        const bool pf = (yq + 1 < y0 + YSEG) && (need_next > loaded_max);
        if (pf) {
            cp16(sdstb + (uint32_t)((need_next % NSLOT) * SLICEB) + ssoff,
                 &gsrc[sgbase + (size_t)need_next * W_ * 64]);
            asm volatile("cp.async.commit_group;");
            loaded_max = need_next;
        }

        int slot[5];
        {
            int s0 = (yc - 2) % NSLOT;
#pragma unroll
            for (int i5 = 0; i5 < 5; i5++) {
                slot[i5] = s0;
                s0 = (s0 + 1 == NSLOT) ? 0 : s0 + 1;
            }
        }

        // Q: fp32 from gmem, convert to half2 once
        const float4* qp = (const float4*)&g_Q[(size_t)(tq * HW_ + yq * W_ + x0 + qx) * CK + hoff];
        float4 qf0 = qp[0], qf1 = qp[1], qf2 = qp[2], qf3 = qp[3];
        __half2 q2[8];
        q2[0] = __float22half2_rn(make_float2(qf0.x, qf0.y));
        q2[1] = __float22half2_rn(make_float2(qf0.z, qf0.w));
        q2[2] = __float22half2_rn(make_float2(qf1.x, qf1.y));
        q2[3] = __float22half2_rn(make_float2(qf1.z, qf1.w));
        q2[4] = __float22half2_rn(make_float2(qf2.x, qf2.y));
        q2[5] = __float22half2_rn(make_float2(qf2.z, qf2.w));
        q2[6] = __float22half2_rn(make_float2(qf3.x, qf3.y));
        q2[7] = __float22half2_rn(make_float2(qf3.z, qf3.w));

        // phase 1: Q.K (fp16 dot, fp32 combine)
        float a[15];
#pragma unroll
        for (int tk = 0; tk < 3; tk++) {
#pragma unroll
            for (int i5 = 0; i5 < 5; i5++) {
                const char* kr = Krh + slot[i5] * SLICEB + (tk * 8 + rl) * HROW + hb;
                uint4 ka = *(const uint4*)kr;
                uint4 kb = *(const uint4*)(kr + 16);
                __half2 s2 = __hmul2(q2[0], H2(ka.x));
                s2 = __hfma2(q2[1], H2(ka.y), s2);
                s2 = __hfma2(q2[2], H2(ka.z), s2);
                s2 = __hfma2(q2[3], H2(ka.w), s2);
                s2 = __hfma2(q2[4], H2(kb.x), s2);
                s2 = __hfma2(q2[5], H2(kb.y), s2);
                s2 = __hfma2(q2[6], H2(kb.z), s2);
                s2 = __hfma2(q2[7], H2(kb.w), s2);
                float2 f = __half22float2(s2);
                a[tk * 5 + i5] = f.x + f.y;
            }
        }

        // Q . sp_emb for this lane's column
        float qsp[5];
#pragma unroll
        for (int i5 = 0; i5 < 5; i5++) {
            const char* sp = SPh + (i5 * 5 + kxrc) * HROW + hb;
            uint4 sa = *(const uint4*)sp;
            uint4 sb2 = *(const uint4*)(sp + 16);
            __half2 s2 = __hmul2(q2[0], H2(sa.x));
            s2 = __hfma2(q2[1], H2(sa.y), s2);
            s2 = __hfma2(q2[2], H2(sa.z), s2);
            s2 = __hfma2(q2[3], H2(sa.w), s2);
            s2 = __hfma2(q2[4], H2(sb2.x), s2);
            s2 = __hfma2(q2[5], H2(sb2.y), s2);
            s2 = __hfma2(q2[6], H2(sb2.z), s2);
            s2 = __hfma2(q2[7], H2(sb2.w), s2);
            float2 f = __half22float2(s2);
            qsp[i5] = f.x + f.y;
        }

        float ssum = 0.f;
#pragma unroll
        for (int tk = 0; tk < 3; tk++)
#pragma unroll
            for (int i5 = 0; i5 < 5; i5++) {
                int idx = tk * 5 + i5;
                float e = ex2((a[idx] + qsp[i5]) * L2S);
                e = valid ? e : 0.f;
                a[idx] = e;
                ssum += e;
            }
        ssum += __shfl_xor_sync(0xffffffffu, ssum, 1);
        ssum += __shfl_xor_sync(0xffffffffu, ssum, 2);
        ssum += __shfl_xor_sync(0xffffffffu, ssum, 4);
        float rs = __fdividef(1.f, ssum);

        // phase 2: AV (fp16 V, fp32 accumulate)
        u64 acc[4][2];
#pragma unroll
        for (int q = 0; q < 4; q++) { acc[q][0] = 0ull; acc[q][1] = 0ull; }

#pragma unroll
        for (int tk = 0; tk < 3; tk++) {
#pragma unroll
            for (int i5 = 0; i5 < 5; i5++) {
                const int idx = tk * 5 + i5;
                const char* vr = Vrh + slot[i5] * SLICEB + (tk * 8 + rl) * HROW + hb + (d4 << 3);
                uint2 vv = *(const uint2*)vr;
                float2 va = __half22float2(H2(vv.x));
                float2 vb = __half22float2(H2(vv.y));
                u64 vx = pack2(va.x, va.y);
                u64 vy = pack2(vb.x, vb.y);
#pragma unroll
                for (int q = 0; q < 4; q++) {
                    float av = __shfl_sync(0xffffffffu, a[idx], (q << 3) | rl);
                    u64 aa = pack2(av, av);
                    acc[q][0] = ffma2(aa, vx, acc[q][0]);
                    acc[q][1] = ffma2(aa, vy, acc[q][1]);
                }
            }
        }
#pragma unroll
        for (int off = 1; off <= 4; off <<= 1) {
#pragma unroll
            for (int q = 0; q < 4; q++) {
                acc[q][0] = fadd2(acc[q][0], __shfl_xor_sync(0xffffffffu, acc[q][0], off));
                acc[q][1] = fadd2(acc[q][1], __shfl_xor_sync(0xffffffffu, acc[q][1], off));
            }
        }
        float rsw = __shfl_sync(0xffffffffu, rs, (lane & 7) * 8);
        if (rl < 4) {
            float2 lo = unpack2(acc[rl][0]);
            float2 hi = unpack2(acc[rl][1]);
            float o0 = lo.x * rsw, o1 = lo.y * rsw, o2 = hi.x * rsw, o3 = hi.y * rsw;
            uint32_t h0, l0, h1, l1;
            split2(o0, o1, h0, l0);
            split2(o2, o3, h1, l1);
            const size_t pi = ((size_t)(tq * HW_ + yq * W_ + x0 + rl) * CK + hoff + d4 * 4) >> 1;
            *(uint2*)&g_Ohi[pi] = make_uint2(h0, h1);
            *(uint2*)&g_Olo[pi] = make_uint2(l0, l1);
        }

        if (pf) asm volatile("cp.async.wait_group 0;");
        __syncthreads();
    }
}

// ---------------------------------------------------------------------------
extern "C" void kernel_launch(void* const* d_in, const int* in_sizes, int n_in,
                              void* d_out, int out_size)
{
    const float* x    = (const float*)d_in[0];
    const float* Wq   = (const float*)d_in[1];
    const float* Wk   = (const float*)d_in[2];
    const float* Wv   = (const float*)d_in[3];
    const float* Wo   = (const float*)d_in[4];
    const float* temp = (const float*)d_in[5];
    const float* sp   = (const float*)d_in[6];
    float* out = (float*)d_out;

    cudaFuncSetAttribute(qkv_mma_kernel, cudaFuncAttributeMaxDynamicSharedMemorySize, GEMM_SMEM);
    cudaFuncSetAttribute(outproj_mma_kernel, cudaFuncAttributeMaxDynamicSharedMemorySize, GEMM_SMEM);
    cudaFuncSetAttribute(attn_kernel, cudaFuncAttributeMaxDynamicSharedMemorySize, ATTN_SMEM);

    xprep_kernel<<<NT * 32 / 256, 256>>>(x);
    wprep_kernel<<<5, 256>>>(Wq, Wk, Wv, Wo, sp);
    qkv_mma_kernel<<<dim3(NT / 128, 3), 256, GEMM_SMEM>>>(temp, sp);

    attn_kernel<<<dim3(XS, YB), 768, ATTN_SMEM>>>();

    outproj_mma_kernel<<<NT / 128, 256, GEMM_SMEM>>>(out);
}

// round 12
// speedup vs baseline: 1.6741x; 1.1596x over previous
#include <cuda_runtime.h>
#include <cuda_fp16.h>
#include <cstdint>

#define T_  3
#define H_  96
#define W_  96
#define C_  128
#define CK  128
#define NHEAD 8
#define DH  16
#define HW_ (H_*W_)
#define NT  (T_*HW_)        // 27648
#define QX  4
#define YSEG 16
#define XS (W_/QX)
#define YB (H_/YSEG)
#define NSLOT 6

// fp16 K/V smem layout: row = 128 halves = 256B data + 16B pad
#define HROW 272
#define SLICEB (24*HROW)
#define ATTN_SMEM (12*SLICEB + 25*HROW)   // 85136

typedef unsigned long long u64;

extern __shared__ char smraw[];

// fp16 packed pairs (half2 per uint32): 64 per row of 128
__device__ uint32_t g_Qh[NT*64], g_Kh[NT*64], g_Vh[NT*64], g_Oh[NT*64];
__device__ uint32_t g_sph[25*64];
__device__ uint32_t g_xh[NT*64];
__device__ uint32_t g_Whh[4][128*64], g_Whl[4][128*64];   // [k][n-pairs], fp16 hi/lo

// ---------------- helpers ----------------
__device__ __forceinline__ u64 ffma2(u64 a, u64 b, u64 c) {
    u64 d; asm("fma.rn.f32x2 %0,%1,%2,%3;" : "=l"(d) : "l"(a), "l"(b), "l"(c)); return d;
}
__device__ __forceinline__ u64 fadd2(u64 a, u64 b) {
    u64 d; asm("add.rn.f32x2 %0,%1,%2;" : "=l"(d) : "l"(a), "l"(b)); return d;
}
__device__ __forceinline__ u64 pack2(float lo, float hi) {
    u64 d; asm("mov.b64 %0,{%1,%2};" : "=l"(d) : "f"(lo), "f"(hi)); return d;
}
__device__ __forceinline__ float2 unpack2(u64 v) {
    float2 r; asm("mov.b64 {%0,%1},%2;" : "=f"(r.x), "=f"(r.y) : "l"(v)); return r;
}
__device__ __forceinline__ void cp16(uint32_t dst, const void* src) {
    asm volatile("cp.async.cg.shared.global [%0], [%1], 16;" :: "r"(dst), "l"(src));
}
__device__ __forceinline__ float ex2(float t) {
    float e; asm("ex2.approx.f32 %0, %1;" : "=f"(e) : "f"(t)); return e;
}
__device__ __forceinline__ uint32_t h2pack(float x0, float x1) {
    __half2 h = __float22half2_rn(make_float2(x0, x1));
    return *reinterpret_cast<uint32_t*>(&h);
}
#define H2(u) (*reinterpret_cast<const __half2*>(&(u)))

// ---------------- mma helpers ----------------
__device__ __forceinline__ void ldsm_x4(uint32_t* a, uint32_t addr) {
    asm volatile("ldmatrix.sync.aligned.m8n8.x4.shared.b16 {%0,%1,%2,%3}, [%4];"
                 : "=r"(a[0]), "=r"(a[1]), "=r"(a[2]), "=r"(a[3]) : "r"(addr));
}
__device__ __forceinline__ void ldsm_x2t(uint32_t* b, uint32_t addr) {
    asm volatile("ldmatrix.sync.aligned.m8n8.x2.trans.shared.b16 {%0,%1}, [%2];"
                 : "=r"(b[0]), "=r"(b[1]) : "r"(addr));
}
__device__ __forceinline__ void mma16816(float* c, const uint32_t* a, const uint32_t* b) {
    asm volatile(
        "mma.sync.aligned.m16n8k16.row.col.f32.f16.f16.f32 "
        "{%0,%1,%2,%3}, {%4,%5,%6,%7}, {%8,%9}, {%0,%1,%2,%3};"
        : "+f"(c[0]), "+f"(c[1]), "+f"(c[2]), "+f"(c[3])
        : "r"(a[0]), "r"(a[1]), "r"(a[2]), "r"(a[3]), "r"(b[0]), "r"(b[1]));
}

#define BROW 272
#define TILE_B (128*BROW)
#define A_OFF  0
#define BH_OFF TILE_B
#define BL_OFF (2*TILE_B)
#define GEMM_SMEM (3*TILE_B)    // 104448

// ---------------------------------------------------------------------------
// prep kernels
// ---------------------------------------------------------------------------
__global__ __launch_bounds__(256) void xprep_kernel(const float* __restrict__ x) {
    int i = blockIdx.x * 256 + threadIdx.x;
    float4 v = *(const float4*)&x[(size_t)i * 4];
    *(uint2*)&g_xh[i * 2] = make_uint2(h2pack(v.x, v.y), h2pack(v.z, v.w));
}

__global__ __launch_bounds__(256) void wprep_kernel(
    const float* __restrict__ Wq, const float* __restrict__ Wk,
    const float* __restrict__ Wv, const float* __restrict__ Wo,
    const float* __restrict__ sp_emb)
{
    const int mat = blockIdx.x;
    if (mat == 4) {
        for (int i = threadIdx.x; i < 25 * 64; i += 256) {
            float2 v = *(const float2*)&sp_emb[(size_t)i * 2];
            g_sph[i] = h2pack(v.x, v.y);
        }
        return;
    }
    const float* Wsrc = (mat == 0) ? Wq : (mat == 1) ? Wk : (mat == 2) ? Wv : Wo;
    for (int p = threadIdx.x; p < 128 * 64; p += 256) {
        float2 v = *(const float2*)&Wsrc[(size_t)p * 2];
        __half h0 = __float2half_rn(v.x);
        __half h1 = __float2half_rn(v.y);
        __half l0 = __float2half_rn(v.x - __half2float(h0));
        __half l1 = __float2half_rn(v.y - __half2float(h1));
        g_Whh[mat][p] = ((uint32_t)__half_as_ushort(h1) << 16) | __half_as_ushort(h0);
        g_Whl[mat][p] = ((uint32_t)__half_as_ushort(l1) << 16) | __half_as_ushort(l0);
    }
}

// ---------------------------------------------------------------------------
// Shared MMA body: fp16 2-pass (A*Bh + A*Bl). c[2][8][4] per warp.
// ---------------------------------------------------------------------------
__device__ __forceinline__ void mma_body(
    const uint32_t* __restrict__ A, int mat, int m0, float c[2][8][4])
{
    const int tid  = threadIdx.x;
    const int w    = tid >> 5;
    const int lane = tid & 31;
    const uint32_t sb = (uint32_t)__cvta_generic_to_shared(smraw);

    // group 1: A + Bh
#pragma unroll
    for (int it = 0; it < 8; it++) {
        int i = tid + it * 256;
        int r = i >> 4, ch = i & 15;
        uint32_t d = (uint32_t)(r * BROW + ch * 16);
        cp16(sb + A_OFF + d, (const char*)A + ((size_t)(m0 + r) * 64 + ch * 4) * 4);
        cp16(sb + BH_OFF + d, (const char*)&g_Whh[mat][r * 64 + ch * 4]);
    }
    asm volatile("cp.async.commit_group;");
    // group 2: Bl
#pragma unroll
    for (int it = 0; it < 8; it++) {
        int i = tid + it * 256;
        int r = i >> 4, ch = i & 15;
        uint32_t d = (uint32_t)(r * BROW + ch * 16);
        cp16(sb + BL_OFF + d, (const char*)&g_Whl[mat][r * 64 + ch * 4]);
    }
    asm volatile("cp.async.commit_group;");

#pragma unroll
    for (int mt = 0; mt < 2; mt++)
#pragma unroll
        for (int nt = 0; nt < 8; nt++)
#pragma unroll
            for (int j = 0; j < 4; j++) c[mt][nt][j] = 0.f;

    const int wm = w & 3, wn = w >> 2;
    const uint32_t aBase = sb + A_OFF + (uint32_t)((wm * 32 + (lane & 15)) * BROW + (lane >> 4) * 16);
    const uint32_t bBase = sb + (uint32_t)((lane & 15) * BROW + wn * 128);
    const uint32_t bOffP[2] = {BH_OFF, BL_OFF};

    asm volatile("cp.async.wait_group 1;");
    __syncthreads();

#pragma unroll
    for (int pass = 0; pass < 2; pass++) {
        if (pass == 1) {
            asm volatile("cp.async.wait_group 0;");
            __syncthreads();
        }
        const uint32_t bT = bBase + bOffP[pass];
#pragma unroll
        for (int k8 = 0; k8 < 8; k8++) {
            uint32_t a[2][4], b[8][2];
#pragma unroll
            for (int mt = 0; mt < 2; mt++)
                ldsm_x4(a[mt], aBase + (uint32_t)(mt * 16 * BROW + k8 * 32));
#pragma unroll
            for (int nt = 0; nt < 8; nt++)
                ldsm_x2t(b[nt], bT + (uint32_t)(k8 * 16 * BROW + nt * 16));
#pragma unroll
            for (int mt = 0; mt < 2; mt++)
#pragma unroll
                for (int nt = 0; nt < 8; nt++)
                    mma16816(c[mt][nt], a[mt], b[nt]);
        }
    }
}

// ---------------------------------------------------------------------------
// Kernel: QKV via mma.sync. Q/K/V -> fp16 half2 pairs. grid (216, 3)
// ---------------------------------------------------------------------------
__global__ __launch_bounds__(256, 1) void qkv_mma_kernel(
    const float* __restrict__ temp_emb, const float* __restrict__ sp_emb)
{
    const int mat = blockIdx.y;
    const int m0 = blockIdx.x * 128;

    float c[2][8][4];
    mma_body(g_xh, mat, m0, c);

    const int w = threadIdx.x >> 5, lane = threadIdx.x & 31;
    const int wm = w & 3, wn = w >> 2;
    uint32_t* dsth = (mat == 0) ? g_Qh : (mat == 1) ? g_Kh : g_Vh;
#pragma unroll
    for (int mt = 0; mt < 2; mt++) {
#pragma unroll
        for (int rh = 0; rh < 2; rh++) {
            const int n   = m0 + wm * 32 + mt * 16 + (lane >> 2) + rh * 8;
            const int t   = n / HW_;
            const int rem = n % HW_;
            int qidx = 0;
            if (mat == 0) {
                const int yq = rem / W_, xq = rem % W_;
                const int yc = min(max(yq, 2), H_ - 3);
                const int xc = min(max(xq, 2), W_ - 3);
                qidx = (yq - yc + 2) * 5 + (xq - xc + 2);
            }
#pragma unroll
            for (int nt = 0; nt < 8; nt++) {
                const int col = wn * 64 + nt * 8 + 2 * (lane & 3);
                float v0 = c[mt][nt][rh * 2 + 0];
                float v1 = c[mt][nt][rh * 2 + 1];
                if (mat <= 1) {
                    v0 += temp_emb[t * CK + col];
                    v1 += temp_emb[t * CK + col + 1];
                }
                if (mat == 0) {
                    v0 += sp_emb[qidx * CK + col];
                    v1 += sp_emb[qidx * CK + col + 1];
                }
                dsth[(size_t)n * 64 + (col >> 1)] = h2pack(v0, v1);
            }
        }
    }
}

// ---------------------------------------------------------------------------
// Kernel: output projection via mma.sync + transposed writeout. grid 216
// ---------------------------------------------------------------------------
__global__ __launch_bounds__(256, 1) void outproj_mma_kernel(float* __restrict__ out)
{
    const int m0 = blockIdx.x * 128;

    float c[2][8][4];
    mma_body(g_Oh, 3, m0, c);

    const int w = threadIdx.x >> 5, lane = threadIdx.x & 31;
    const int wm = w & 3, wn = w >> 2;
#pragma unroll
    for (int mt = 0; mt < 2; mt++) {
#pragma unroll
        for (int rh = 0; rh < 2; rh++) {
            const int n   = m0 + wm * 32 + mt * 16 + (lane >> 2) + rh * 8;
            const int t   = n / HW_;
            const int rem = n % HW_;
            const size_t ob = (size_t)rem * (T_ * C_) + t * C_;
#pragma unroll
            for (int nt = 0; nt < 8; nt++) {
                const int col = wn * 64 + nt * 8 + 2 * (lane & 3);
                *(float2*)&out[ob + col] =
                    make_float2(c[mt][nt][rh * 2 + 0], c[mt][nt][rh * 2 + 1]);
            }
        }
    }
}

// ---------------------------------------------------------------------------
// Kernel: attention, rolling-window persistent blocks, fp16 everywhere.
// ---------------------------------------------------------------------------
__global__ __launch_bounds__(768) void attn_kernel()
{
    char* Krh = smraw;                       // 6 x SLICEB
    char* Vrh = smraw + 6 * SLICEB;          // 6 x SLICEB
    char* SPh = smraw + 12 * SLICEB;         // 25 x HROW

    const uint32_t sbase = (uint32_t)__cvta_generic_to_shared(smraw);
    const uint32_t Kb0 = sbase;
    const uint32_t Vb0 = sbase + 6 * SLICEB;
    const uint32_t SPb = sbase + 12 * SLICEB;

    const int x0  = blockIdx.x * QX;
    const int y0  = blockIdx.y * YSEG;
    const int tid = threadIdx.x;
    const int xbase = min(max(x0, 2), W_ - 3) - 2;

    const bool isV = tid >= 384;
    const int j    = isV ? tid - 384 : tid;
    const int grow = j >> 4;
    const int gch  = j & 15;
    const int gt   = grow >> 3;
    const int gcol = min(xbase + (grow & 7), W_ - 1);
    const size_t sgbase = (size_t)(gt * HW_ + gcol) * 64 + gch * 4;
    const uint32_t ssoff = (uint32_t)(grow * HROW + gch * 16);
    const uint32_t* gsrc = isV ? g_Vh : g_Kh;
    const uint32_t sdstb = isV ? Vb0 : Kb0;

    if (tid < 400) {
        int r = tid >> 4, ch = tid & 15;
        cp16(SPb + (uint32_t)(r * HROW + ch * 16), &g_sph[r * 64 + ch * 4]);
    }
    const int yc0 = min(max(y0, 2), H_ - 3);
#pragma unroll
    for (int r = 0; r < 5; r++) {
        const int yr = yc0 - 2 + r;
        cp16(sdstb + (uint32_t)((yr % NSLOT) * SLICEB) + ssoff,
             &gsrc[sgbase + (size_t)yr * W_ * 64]);
    }
    asm volatile("cp.async.commit_group;");
    asm volatile("cp.async.wait_group 0;");
    __syncthreads();
    int loaded_max = yc0 + 2;

    const int lane = tid & 31;
    const int w    = tid >> 5;
    const int tq   = w / NHEAD;
    const int h    = w % NHEAD;
    const int hb   = h << 5;        // byte offset within fp16 row

    const int qx  = lane >> 3;
    const int rl  = lane & 7;
    const int xoffq = min(max(x0 + qx, 2), W_ - 3) - 2 - xbase;
    const int kxr   = rl - xoffq;
    const bool valid = (kxr >= 0) && (kxr <= 4);
    const int kxrc  = min(max(kxr, 0), 4);
    const int d4 = lane >> 3;

    const float L2S = 0.36067376022224085f;   // 0.25 * log2(e)

    for (int yq = y0; yq < y0 + YSEG; yq++) {
        const int yc = min(max(yq, 2), H_ - 3);

        const int need_next = min(max(yq + 1, 2), H_ - 3) + 2;
        const bool pf = (yq + 1 < y0 + YSEG) && (need_next > loaded_max);
        if (pf) {
            cp16(sdstb + (uint32_t)((need_next % NSLOT) * SLICEB) + ssoff,
                 &gsrc[sgbase + (size_t)need_next * W_ * 64]);
            asm volatile("cp.async.commit_group;");
            loaded_max = need_next;
        }

        int slot[5];
        {
            int s0 = (yc - 2) % NSLOT;
#pragma unroll
            for (int i5 = 0; i5 < 5; i5++) {
                slot[i5] = s0;
                s0 = (s0 + 1 == NSLOT) ? 0 : s0 + 1;
            }
        }

        // Q: fp16 direct from gmem (2 x LDG.128)
        const uint4* qp = (const uint4*)&g_Qh[(size_t)(tq * HW_ + yq * W_ + x0 + qx) * 64 + (h << 3)];
        uint4 qa = qp[0], qb = qp[1];
        __half2 q2[8] = {H2(qa.x), H2(qa.y), H2(qa.z), H2(qa.w),
                         H2(qb.x), H2(qb.y), H2(qb.z), H2(qb.w)};

        // phase 1: Q.K (fp16 dot, fp32 combine)
        float a[15];
#pragma unroll
        for (int tk = 0; tk < 3; tk++) {
#pragma unroll
            for (int i5 = 0; i5 < 5; i5++) {
                const char* kr = Krh + slot[i5] * SLICEB + (tk * 8 + rl) * HROW + hb;
                uint4 ka = *(const uint4*)kr;
                uint4 kb = *(const uint4*)(kr + 16);
                __half2 s2 = __hmul2(q2[0], H2(ka.x));
                s2 = __hfma2(q2[1], H2(ka.y), s2);
                s2 = __hfma2(q2[2], H2(ka.z), s2);
                s2 = __hfma2(q2[3], H2(ka.w), s2);
                s2 = __hfma2(q2[4], H2(kb.x), s2);
                s2 = __hfma2(q2[5], H2(kb.y), s2);
                s2 = __hfma2(q2[6], H2(kb.z), s2);
                s2 = __hfma2(q2[7], H2(kb.w), s2);
                float2 f = __half22float2(s2);
                a[tk * 5 + i5] = f.x + f.y;
            }
        }

        float qsp[5];
#pragma unroll
        for (int i5 = 0; i5 < 5; i5++) {
            const char* sp = SPh + (i5 * 5 + kxrc) * HROW + hb;
            uint4 sa = *(const uint4*)sp;
            uint4 sb2 = *(const uint4*)(sp + 16);
            __half2 s2 = __hmul2(q2[0], H2(sa.x));
            s2 = __hfma2(q2[1], H2(sa.y), s2);
            s2 = __hfma2(q2[2], H2(sa.z), s2);
            s2 = __hfma2(q2[3], H2(sa.w), s2);
            s2 = __hfma2(q2[4], H2(sb2.x), s2);
            s2 = __hfma2(q2[5], H2(sb2.y), s2);
            s2 = __hfma2(q2[6], H2(sb2.z), s2);
            s2 = __hfma2(q2[7], H2(sb2.w), s2);
            float2 f = __half22float2(s2);
            qsp[i5] = f.x + f.y;
        }

        float ssum = 0.f;
#pragma unroll
        for (int tk = 0; tk < 3; tk++)
#pragma unroll
            for (int i5 = 0; i5 < 5; i5++) {
                int idx = tk * 5 + i5;
                float e = ex2((a[idx] + qsp[i5]) * L2S);
                e = valid ? e : 0.f;
                a[idx] = e;
                ssum += e;
            }
        ssum += __shfl_xor_sync(0xffffffffu, ssum, 1);
        ssum += __shfl_xor_sync(0xffffffffu, ssum, 2);
        ssum += __shfl_xor_sync(0xffffffffu, ssum, 4);
        float rs = __fdividef(1.f, ssum);

        // phase 2: AV (fp16 V, fp32 accumulate)
        u64 acc[4][2];
#pragma unroll
        for (int q = 0; q < 4; q++) { acc[q][0] = 0ull; acc[q][1] = 0ull; }

#pragma unroll
        for (int tk = 0; tk < 3; tk++) {
#pragma unroll
            for (int i5 = 0; i5 < 5; i5++) {
                const int idx = tk * 5 + i5;
                const char* vr = Vrh + slot[i5] * SLICEB + (tk * 8 + rl) * HROW + hb + (d4 << 3);
                uint2 vv = *(const uint2*)vr;
                float2 va = __half22float2(H2(vv.x));
                float2 vb = __half22float2(H2(vv.y));
                u64 vx = pack2(va.x, va.y);
                u64 vy = pack2(vb.x, vb.y);
#pragma unroll
                for (int q = 0; q < 4; q++) {
                    float av = __shfl_sync(0xffffffffu, a[idx], (q << 3) | rl);
                    u64 aa = pack2(av, av);
                    acc[q][0] = ffma2(aa, vx, acc[q][0]);
                    acc[q][1] = ffma2(aa, vy, acc[q][1]);
                }
            }
        }
#pragma unroll
        for (int off = 1; off <= 4; off <<= 1) {
#pragma unroll
            for (int q = 0; q < 4; q++) {
                acc[q][0] = fadd2(acc[q][0], __shfl_xor_sync(0xffffffffu, acc[q][0], off));
                acc[q][1] = fadd2(acc[q][1], __shfl_xor_sync(0xffffffffu, acc[q][1], off));
            }
        }
        float rsw = __shfl_sync(0xffffffffu, rs, (lane & 7) * 8);
        if (rl < 4) {
            float2 lo = unpack2(acc[rl][0]);
            float2 hi = unpack2(acc[rl][1]);
            const int n = tq * HW_ + yq * W_ + x0 + rl;
            *(uint2*)&g_Oh[(size_t)n * 64 + (h << 3) + d4 * 2] =
                make_uint2(h2pack(lo.x * rsw, lo.y * rsw),
                           h2pack(hi.x * rsw, hi.y * rsw));
        }

        if (pf) asm volatile("cp.async.wait_group 0;");
        __syncthreads();
    }
}

// ---------------------------------------------------------------------------
extern "C" void kernel_launch(void* const* d_in, const int* in_sizes, int n_in,
                              void* d_out, int out_size)
{
    const float* x    = (const float*)d_in[0];
    const float* Wq   = (const float*)d_in[1];
    const float* Wk   = (const float*)d_in[2];
    const float* Wv   = (const float*)d_in[3];
    const float* Wo   = (const float*)d_in[4];
    const float* temp = (const float*)d_in[5];
    const float* sp   = (const float*)d_in[6];
    float* out = (float*)d_out;

    cudaFuncSetAttribute(qkv_mma_kernel, cudaFuncAttributeMaxDynamicSharedMemorySize, GEMM_SMEM);
    cudaFuncSetAttribute(outproj_mma_kernel, cudaFuncAttributeMaxDynamicSharedMemorySize, GEMM_SMEM);
    cudaFuncSetAttribute(attn_kernel, cudaFuncAttributeMaxDynamicSharedMemorySize, ATTN_SMEM);

    xprep_kernel<<<NT * 32 / 256, 256>>>(x);
    wprep_kernel<<<5, 256>>>(Wq, Wk, Wv, Wo, sp);
    qkv_mma_kernel<<<dim3(NT / 128, 3), 256, GEMM_SMEM>>>(temp, sp);

    attn_kernel<<<dim3(XS, YB), 768, ATTN_SMEM>>>();

    outproj_mma_kernel<<<NT / 128, 256, GEMM_SMEM>>>(out);
}